// round 4
// baseline (speedup 1.0000x reference)
#include <cuda_runtime.h>
#include <cuda_fp16.h>
#include <climits>

#define BB 4
#define NN 65536
#define HH 128
#define WW 128
#define C_ALL 448          // 64 + 128 + 256
#define RGW 68             // max smem region extent (texels)
#define NCHUNK 28          // 28 chunks x 16 channels
#define NSPLIT 4
#define PTS_PER_BLOCK (NN / NSPLIT)   // 16384
#define ROUND 256
#define NROUNDS (PTS_PER_BLOCK / ROUND)

// smem layout (bytes): region 68*68*16*2 = 147968 | s_wt 4*256*4 = 4096 |
//                      s_off 4*256*4 = 4096 | s_val 2*256*17*4 = 34816
#define SM_REGION_H2 (RGW * RGW * 8)          // half2 count
#define SMEM_BYTES (147968 + 4096 + 4096 + 34816)   // 190976

__device__ float g_grid0[BB * NN];
__device__ float g_grid1[BB * NN];
__device__ int   g_bbox[BB][4];   // min x0, min y0, max x1, max y1
__device__ int   g_needs_mlp;

// ---------------------------------------------------------------------------
__global__ void check_wr_kernel(const float* __restrict__ Wr) {
    if (threadIdx.x < BB) {
        g_bbox[threadIdx.x][0] = INT_MAX;
        g_bbox[threadIdx.x][1] = INT_MAX;
        g_bbox[threadIdx.x][2] = INT_MIN;
        g_bbox[threadIdx.x][3] = INT_MIN;
    }
    int nz = 0;
    for (int idx = threadIdx.x; idx < 2 * 131; idx += blockDim.x) {
        int k = idx % 131;
        if (k >= 3 && Wr[idx] != 0.0f) nz = 1;
    }
    int any = __syncthreads_or(nz);
    if (threadIdx.x == 0) g_needs_mlp = any;
}

// ---------------------------------------------------------------------------
__global__ void base_grid_kernel(const float* __restrict__ x_loc,
                                 const float* __restrict__ Wr,
                                 const float* __restrict__ br) {
    int idx = blockIdx.x * blockDim.x + threadIdx.x;
    if (idx >= BB * NN) return;
    int b = idx >> 16;
    int n = idx & (NN - 1);
    float x0 = x_loc[(b * 3 + 0) * NN + n];
    float x1 = x_loc[(b * 3 + 1) * NN + n];
    float x2 = x_loc[(b * 3 + 2) * NN + n];
    g_grid0[idx] = br[0] + Wr[0] * x0 + Wr[1] * x1 + Wr[2] * x2;
    g_grid1[idx] = br[1] + Wr[131] * x0 + Wr[132] * x1 + Wr[133] * x2;
}

// ---------------------------------------------------------------------------
// Fallback MLP path (early-exits for the benched inputs where Wr[:,3:]==0).
// ---------------------------------------------------------------------------
__global__ void mlp_grid_kernel(const float* __restrict__ x_loc,
                                const float* __restrict__ x_feat,
                                const float* __restrict__ W1,
                                const float* __restrict__ b1,
                                const float* __restrict__ W2,
                                const float* __restrict__ b2,
                                const float* __restrict__ Wr) {
    if (g_needs_mlp == 0) return;
    int idx = blockIdx.x * blockDim.x + threadIdx.x;
    if (idx >= BB * NN) return;
    int b = idx >> 16;
    int n = idx & (NN - 1);

    float x[67];
    for (int k = 0; k < 3; k++)  x[k] = x_loc[(b * 3 + k) * NN + n];
    for (int k = 0; k < 64; k++) x[3 + k] = x_feat[(b * 64 + k) * NN + n];

    float h1[128];
    for (int j = 0; j < 128; j++) {
        float s = b1[j];
        for (int k = 0; k < 67; k++) s += W1[j * 67 + k] * x[k];
        h1[j] = fmaxf(s, 0.0f);
    }
    float g0 = 0.0f, g1 = 0.0f;
    for (int j = 0; j < 128; j++) {
        float s = b2[j];
        for (int k = 0; k < 128; k++) s += W2[j * 128 + k] * h1[k];
        s = fmaxf(s, 0.0f);
        g0 += Wr[3 + j] * s;
        g1 += Wr[131 + 3 + j] * s;
    }
    g_grid0[idx] += g0;
    g_grid1[idx] += g1;
}

// ---------------------------------------------------------------------------
__device__ __forceinline__ void point_coords(float gx, float gy,
                                             int& x0, int& x1, int& y0, int& y1,
                                             float& wx, float& wy) {
    float ix = ((gx + 1.0f) * 128.0f - 1.0f) * 0.5f;
    float iy = ((gy + 1.0f) * 128.0f - 1.0f) * 0.5f;
    ix = fminf(fmaxf(ix, 0.0f), 127.0f);
    iy = fminf(fmaxf(iy, 0.0f), 127.0f);
    float fx0 = floorf(ix), fy0 = floorf(iy);
    wx = ix - fx0; wy = iy - fy0;
    x0 = (int)fx0; y0 = (int)fy0;
    x1 = min(x0 + 1, 127); y1 = min(y0 + 1, 127);
}

// ---------------------------------------------------------------------------
// Per-batch bbox of all referenced texels (warp-reduced atomics).
// ---------------------------------------------------------------------------
__global__ void bbox_kernel() {
    int idx = blockIdx.x * blockDim.x + threadIdx.x;
    if (idx >= BB * NN) return;
    int b = idx >> 16;
    int x0, x1, y0, y1; float wx, wy;
    point_coords(g_grid0[idx], g_grid1[idx], x0, x1, y0, y1, wx, wy);
    int mnx = __reduce_min_sync(0xffffffffu, x0);
    int mny = __reduce_min_sync(0xffffffffu, y0);
    int mxx = __reduce_max_sync(0xffffffffu, x1);
    int mxy = __reduce_max_sync(0xffffffffu, y1);
    if ((threadIdx.x & 31) == 0) {   // whole warp is same batch (NN % 32 == 0)
        atomicMin(&g_bbox[b][0], mnx);
        atomicMin(&g_bbox[b][1], mny);
        atomicMax(&g_bbox[b][2], mxx);
        atomicMax(&g_bbox[b][3], mxy);
    }
}

// ---------------------------------------------------------------------------
// Sampler: one block = (n-split, 16-channel chunk, batch).
// Loads the referenced texel region (fp16, [y][x][c16]) into smem straight
// from the NCHW fp32 map, then streams points: stage coords -> smem gather
// -> coalesced streaming writes. Block-uniform global-read fallback if the
// region exceeds RGW x RGW.
// ---------------------------------------------------------------------------
__global__ void __launch_bounds__(512) sample_kernel(
        const float* __restrict__ m0, const float* __restrict__ m1,
        const float* __restrict__ m2, float* __restrict__ out) {
    int chunk = blockIdx.y, b = blockIdx.z;
    int c0 = chunk * 16;
    const float* m; int C, coff;
    if (c0 < 64)       { m = m0; C = 64;  coff = c0; }
    else if (c0 < 192) { m = m1; C = 128; coff = c0 - 64; }
    else               { m = m2; C = 256; coff = c0 - 192; }

    int bx0 = g_bbox[b][0], by0 = g_bbox[b][1];
    int bw = g_bbox[b][2] - bx0 + 1;
    int bh = g_bbox[b][3] - by0 + 1;
    bool use_smem = (bw <= RGW) && (bh <= RGW);

    extern __shared__ __align__(16) char smraw[];
    __half2* region = (__half2*)smraw;
    float*   s_wt   = (float*)(smraw + 147968);            // [4][ROUND]
    int*     s_off  = (int*)(smraw + 147968 + 4096);       // [4][ROUND]
    float*   s_val  = (float*)(smraw + 147968 + 8192);     // [2][ROUND][17]

    int tid = threadIdx.x;
    int lane = tid & 31, w = tid >> 5;

    if (use_smem) {
        __half* rh = (__half*)region;
        int total = 16 * bh * bw;
        for (int i = tid; i < total; i += 512) {
            int x = i % bw;
            int t = i / bw;
            int y = t % bh;
            int c = t / bh;
            float v = m[((size_t)(b * C + coff + c) * HH + (by0 + y)) * WW + bx0 + x];
            rh[(y * RGW + x) * 16 + c] = __float2half(v);
        }
    }

    int nbase = blockIdx.x * PTS_PER_BLOCK;
    int cpair = lane & 7;

    // --- stage round 0 ---
    __syncthreads();
    if (tid < ROUND) {
        int idx = b * NN + nbase + tid;
        int x0, x1, y0, y1; float wx, wy;
        point_coords(g_grid0[idx], g_grid1[idx], x0, x1, y0, y1, wx, wy);
        s_wt[0 * ROUND + tid] = (1.0f - wy) * (1.0f - wx);
        s_wt[1 * ROUND + tid] = (1.0f - wy) * wx;
        s_wt[2 * ROUND + tid] = wy * (1.0f - wx);
        s_wt[3 * ROUND + tid] = wy * wx;
        if (use_smem) {
            s_off[0 * ROUND + tid] = ((y0 - by0) * RGW + (x0 - bx0)) * 8;
            s_off[1 * ROUND + tid] = ((y0 - by0) * RGW + (x1 - bx0)) * 8;
            s_off[2 * ROUND + tid] = ((y1 - by0) * RGW + (x0 - bx0)) * 8;
            s_off[3 * ROUND + tid] = ((y1 - by0) * RGW + (x1 - bx0)) * 8;
        } else {
            s_off[0 * ROUND + tid] = y0 * WW + x0;
            s_off[1 * ROUND + tid] = y0 * WW + x1;
            s_off[2 * ROUND + tid] = y1 * WW + x0;
            s_off[3 * ROUND + tid] = y1 * WW + x1;
        }
    }
    __syncthreads();

    for (int r = 0; r < NROUNDS; r++) {
        int n0 = nbase + r * ROUND;
        float* val = s_val + (r & 1) * (ROUND * 17);

        // --- gather into val ---
        if (use_smem) {
#pragma unroll
            for (int pass = 0; pass < 4; pass++) {
                int p = pass * 64 + (w << 2) + (lane >> 3);
                float w0 = s_wt[p],            w1 = s_wt[ROUND + p];
                float w2 = s_wt[2 * ROUND + p], w3 = s_wt[3 * ROUND + p];
                float2 a  = __half22float2(region[s_off[p] + cpair]);
                float2 bq = __half22float2(region[s_off[ROUND + p] + cpair]);
                float2 cq = __half22float2(region[s_off[2 * ROUND + p] + cpair]);
                float2 dq = __half22float2(region[s_off[3 * ROUND + p] + cpair]);
                val[p * 17 + 2 * cpair]     = w0 * a.x + w1 * bq.x + w2 * cq.x + w3 * dq.x;
                val[p * 17 + 2 * cpair + 1] = w0 * a.y + w1 * bq.y + w2 * cq.y + w3 * dq.y;
            }
        } else {
            const float* mc0 = m + (size_t)(b * C + coff + 2 * cpair) * (HH * WW);
            const float* mc1 = mc0 + HH * WW;
#pragma unroll
            for (int pass = 0; pass < 4; pass++) {
                int p = pass * 64 + (w << 2) + (lane >> 3);
                float ax = 0.0f, ay = 0.0f;
#pragma unroll
                for (int t = 0; t < 4; t++) {
                    int o = s_off[t * ROUND + p];
                    float wt = s_wt[t * ROUND + p];
                    ax += wt * mc0[o];
                    ay += wt * mc1[o];
                }
                val[p * 17 + 2 * cpair]     = ax;
                val[p * 17 + 2 * cpair + 1] = ay;
            }
        }
        __syncthreads();

        // --- stage round r+1 (overlaps the write phase; touches only s_wt/s_off)
        if (r + 1 < NROUNDS && tid < ROUND) {
            int idx = b * NN + n0 + ROUND + tid;
            int x0, x1, y0, y1; float wx, wy;
            point_coords(g_grid0[idx], g_grid1[idx], x0, x1, y0, y1, wx, wy);
            s_wt[0 * ROUND + tid] = (1.0f - wy) * (1.0f - wx);
            s_wt[1 * ROUND + tid] = (1.0f - wy) * wx;
            s_wt[2 * ROUND + tid] = wy * (1.0f - wx);
            s_wt[3 * ROUND + tid] = wy * wx;
            if (use_smem) {
                s_off[0 * ROUND + tid] = ((y0 - by0) * RGW + (x0 - bx0)) * 8;
                s_off[1 * ROUND + tid] = ((y0 - by0) * RGW + (x1 - bx0)) * 8;
                s_off[2 * ROUND + tid] = ((y1 - by0) * RGW + (x0 - bx0)) * 8;
                s_off[3 * ROUND + tid] = ((y1 - by0) * RGW + (x1 - bx0)) * 8;
            } else {
                s_off[0 * ROUND + tid] = y0 * WW + x0;
                s_off[1 * ROUND + tid] = y0 * WW + x1;
                s_off[2 * ROUND + tid] = y1 * WW + x0;
                s_off[3 * ROUND + tid] = y1 * WW + x1;
            }
        }

        // --- write: warp w owns channel c0 + w, n coalesced ---
        float* op = out + ((size_t)(b * C_ALL + c0 + w)) * NN + n0;
#pragma unroll
        for (int i = 0; i < 8; i++)
            __stcs(&op[i * 32 + lane], val[(i * 32 + lane) * 17 + w]);
        __syncthreads();
    }
}

// ---------------------------------------------------------------------------
extern "C" void kernel_launch(void* const* d_in, const int* in_sizes, int n_in,
                              void* d_out, int out_size) {
    const float* x_loc  = (const float*)d_in[0];
    const float* x_feat = (const float*)d_in[1];
    const float* m0     = (const float*)d_in[2];
    const float* m1     = (const float*)d_in[3];
    const float* m2     = (const float*)d_in[4];
    const float* W1     = (const float*)d_in[5];
    const float* b1     = (const float*)d_in[6];
    const float* W2     = (const float*)d_in[7];
    const float* b2     = (const float*)d_in[8];
    const float* Wr     = (const float*)d_in[9];
    const float* br     = (const float*)d_in[10];
    float* out = (float*)d_out;

    cudaFuncSetAttribute(sample_kernel,
                         cudaFuncAttributeMaxDynamicSharedMemorySize, SMEM_BYTES);

    check_wr_kernel<<<1, 256>>>(Wr);
    base_grid_kernel<<<(BB * NN) / 256, 256>>>(x_loc, Wr, br);
    mlp_grid_kernel<<<(BB * NN) / 256, 256>>>(x_loc, x_feat, W1, b1, W2, b2, Wr);
    bbox_kernel<<<(BB * NN) / 256, 256>>>();
    sample_kernel<<<dim3(NSPLIT, NCHUNK, BB), 512, SMEM_BYTES>>>(m0, m1, m2, out);
}

// round 5
// speedup vs baseline: 1.0014x; 1.0014x over previous
#include <cuda_runtime.h>
#include <cuda_fp16.h>
#include <climits>

#define BB 4
#define NN 65536
#define HH 128
#define WW 128
#define C_ALL 448          // 64 + 128 + 256
#define RGW 68             // max smem region extent (texels)
#define NCHUNK 28          // 28 chunks x 16 channels
#define NSPLIT 4
#define PTS_PER_BLOCK (NN / NSPLIT)   // 16384
#define ROUND 256
#define NROUNDS (PTS_PER_BLOCK / ROUND)

// smem layout (bytes): region 68*68*16*2 = 147968 | s_wt 4*256*4 = 4096 |
//                      s_off 4*256*4 = 4096 | s_val 2*256*17*4 = 34816
#define SM_REGION_H2 (RGW * RGW * 8)          // half2 count
#define SMEM_BYTES (147968 + 4096 + 4096 + 34816)   // 190976

__device__ float g_grid0[BB * NN];
__device__ float g_grid1[BB * NN];
__device__ int   g_bbox[BB][4];   // min x0, min y0, max x1, max y1
__device__ int   g_needs_mlp;

// ---------------------------------------------------------------------------
__global__ void check_wr_kernel(const float* __restrict__ Wr) {
    if (threadIdx.x < BB) {
        g_bbox[threadIdx.x][0] = INT_MAX;
        g_bbox[threadIdx.x][1] = INT_MAX;
        g_bbox[threadIdx.x][2] = INT_MIN;
        g_bbox[threadIdx.x][3] = INT_MIN;
    }
    int nz = 0;
    for (int idx = threadIdx.x; idx < 2 * 131; idx += blockDim.x) {
        int k = idx % 131;
        if (k >= 3 && Wr[idx] != 0.0f) nz = 1;
    }
    int any = __syncthreads_or(nz);
    if (threadIdx.x == 0) g_needs_mlp = any;
}

// ---------------------------------------------------------------------------
__global__ void base_grid_kernel(const float* __restrict__ x_loc,
                                 const float* __restrict__ Wr,
                                 const float* __restrict__ br) {
    int idx = blockIdx.x * blockDim.x + threadIdx.x;
    if (idx >= BB * NN) return;
    int b = idx >> 16;
    int n = idx & (NN - 1);
    float x0 = x_loc[(b * 3 + 0) * NN + n];
    float x1 = x_loc[(b * 3 + 1) * NN + n];
    float x2 = x_loc[(b * 3 + 2) * NN + n];
    g_grid0[idx] = br[0] + Wr[0] * x0 + Wr[1] * x1 + Wr[2] * x2;
    g_grid1[idx] = br[1] + Wr[131] * x0 + Wr[132] * x1 + Wr[133] * x2;
}

// ---------------------------------------------------------------------------
// Fallback MLP path (early-exits for the benched inputs where Wr[:,3:]==0).
// ---------------------------------------------------------------------------
__global__ void mlp_grid_kernel(const float* __restrict__ x_loc,
                                const float* __restrict__ x_feat,
                                const float* __restrict__ W1,
                                const float* __restrict__ b1,
                                const float* __restrict__ W2,
                                const float* __restrict__ b2,
                                const float* __restrict__ Wr) {
    if (g_needs_mlp == 0) return;
    int idx = blockIdx.x * blockDim.x + threadIdx.x;
    if (idx >= BB * NN) return;
    int b = idx >> 16;
    int n = idx & (NN - 1);

    float x[67];
    for (int k = 0; k < 3; k++)  x[k] = x_loc[(b * 3 + k) * NN + n];
    for (int k = 0; k < 64; k++) x[3 + k] = x_feat[(b * 64 + k) * NN + n];

    float h1[128];
    for (int j = 0; j < 128; j++) {
        float s = b1[j];
        for (int k = 0; k < 67; k++) s += W1[j * 67 + k] * x[k];
        h1[j] = fmaxf(s, 0.0f);
    }
    float g0 = 0.0f, g1 = 0.0f;
    for (int j = 0; j < 128; j++) {
        float s = b2[j];
        for (int k = 0; k < 128; k++) s += W2[j * 128 + k] * h1[k];
        s = fmaxf(s, 0.0f);
        g0 += Wr[3 + j] * s;
        g1 += Wr[131 + 3 + j] * s;
    }
    g_grid0[idx] += g0;
    g_grid1[idx] += g1;
}

// ---------------------------------------------------------------------------
__device__ __forceinline__ void point_coords(float gx, float gy,
                                             int& x0, int& x1, int& y0, int& y1,
                                             float& wx, float& wy) {
    float ix = ((gx + 1.0f) * 128.0f - 1.0f) * 0.5f;
    float iy = ((gy + 1.0f) * 128.0f - 1.0f) * 0.5f;
    ix = fminf(fmaxf(ix, 0.0f), 127.0f);
    iy = fminf(fmaxf(iy, 0.0f), 127.0f);
    float fx0 = floorf(ix), fy0 = floorf(iy);
    wx = ix - fx0; wy = iy - fy0;
    x0 = (int)fx0; y0 = (int)fy0;
    x1 = min(x0 + 1, 127); y1 = min(y0 + 1, 127);
}

// ---------------------------------------------------------------------------
// Per-batch bbox of all referenced texels (warp-reduced atomics).
// ---------------------------------------------------------------------------
__global__ void bbox_kernel() {
    int idx = blockIdx.x * blockDim.x + threadIdx.x;
    if (idx >= BB * NN) return;
    int b = idx >> 16;
    int x0, x1, y0, y1; float wx, wy;
    point_coords(g_grid0[idx], g_grid1[idx], x0, x1, y0, y1, wx, wy);
    int mnx = __reduce_min_sync(0xffffffffu, x0);
    int mny = __reduce_min_sync(0xffffffffu, y0);
    int mxx = __reduce_max_sync(0xffffffffu, x1);
    int mxy = __reduce_max_sync(0xffffffffu, y1);
    if ((threadIdx.x & 31) == 0) {   // whole warp is same batch (NN % 32 == 0)
        atomicMin(&g_bbox[b][0], mnx);
        atomicMin(&g_bbox[b][1], mny);
        atomicMax(&g_bbox[b][2], mxx);
        atomicMax(&g_bbox[b][3], mxy);
    }
}

// ---------------------------------------------------------------------------
// Sampler: one block = (n-split, 16-channel chunk, batch).
// Loads the referenced texel region (fp16, [y][x][c16]) into smem straight
// from the NCHW fp32 map, then streams points: stage coords -> smem gather
// -> coalesced streaming writes. Block-uniform global-read fallback if the
// region exceeds RGW x RGW.
// ---------------------------------------------------------------------------
__global__ void __launch_bounds__(512) sample_kernel(
        const float* __restrict__ m0, const float* __restrict__ m1,
        const float* __restrict__ m2, float* __restrict__ out) {
    int chunk = blockIdx.y, b = blockIdx.z;
    int c0 = chunk * 16;
    const float* m; int C, coff;
    if (c0 < 64)       { m = m0; C = 64;  coff = c0; }
    else if (c0 < 192) { m = m1; C = 128; coff = c0 - 64; }
    else               { m = m2; C = 256; coff = c0 - 192; }

    int bx0 = g_bbox[b][0], by0 = g_bbox[b][1];
    int bw = g_bbox[b][2] - bx0 + 1;
    int bh = g_bbox[b][3] - by0 + 1;
    bool use_smem = (bw <= RGW) && (bh <= RGW);

    extern __shared__ __align__(16) char smraw[];
    __half2* region = (__half2*)smraw;
    float*   s_wt   = (float*)(smraw + 147968);            // [4][ROUND]
    int*     s_off  = (int*)(smraw + 147968 + 4096);       // [4][ROUND]
    float*   s_val  = (float*)(smraw + 147968 + 8192);     // [2][ROUND][17]

    int tid = threadIdx.x;
    int lane = tid & 31, w = tid >> 5;

    if (use_smem) {
        __half* rh = (__half*)region;
        int total = 16 * bh * bw;
        for (int i = tid; i < total; i += 512) {
            int x = i % bw;
            int t = i / bw;
            int y = t % bh;
            int c = t / bh;
            float v = m[((size_t)(b * C + coff + c) * HH + (by0 + y)) * WW + bx0 + x];
            rh[(y * RGW + x) * 16 + c] = __float2half(v);
        }
    }

    int nbase = blockIdx.x * PTS_PER_BLOCK;
    int cpair = lane & 7;

    // --- stage round 0 ---
    __syncthreads();
    if (tid < ROUND) {
        int idx = b * NN + nbase + tid;
        int x0, x1, y0, y1; float wx, wy;
        point_coords(g_grid0[idx], g_grid1[idx], x0, x1, y0, y1, wx, wy);
        s_wt[0 * ROUND + tid] = (1.0f - wy) * (1.0f - wx);
        s_wt[1 * ROUND + tid] = (1.0f - wy) * wx;
        s_wt[2 * ROUND + tid] = wy * (1.0f - wx);
        s_wt[3 * ROUND + tid] = wy * wx;
        if (use_smem) {
            s_off[0 * ROUND + tid] = ((y0 - by0) * RGW + (x0 - bx0)) * 8;
            s_off[1 * ROUND + tid] = ((y0 - by0) * RGW + (x1 - bx0)) * 8;
            s_off[2 * ROUND + tid] = ((y1 - by0) * RGW + (x0 - bx0)) * 8;
            s_off[3 * ROUND + tid] = ((y1 - by0) * RGW + (x1 - bx0)) * 8;
        } else {
            s_off[0 * ROUND + tid] = y0 * WW + x0;
            s_off[1 * ROUND + tid] = y0 * WW + x1;
            s_off[2 * ROUND + tid] = y1 * WW + x0;
            s_off[3 * ROUND + tid] = y1 * WW + x1;
        }
    }
    __syncthreads();

    for (int r = 0; r < NROUNDS; r++) {
        int n0 = nbase + r * ROUND;
        float* val = s_val + (r & 1) * (ROUND * 17);

        // --- gather into val ---
        if (use_smem) {
#pragma unroll
            for (int pass = 0; pass < 4; pass++) {
                int p = pass * 64 + (w << 2) + (lane >> 3);
                float w0 = s_wt[p],            w1 = s_wt[ROUND + p];
                float w2 = s_wt[2 * ROUND + p], w3 = s_wt[3 * ROUND + p];
                float2 a  = __half22float2(region[s_off[p] + cpair]);
                float2 bq = __half22float2(region[s_off[ROUND + p] + cpair]);
                float2 cq = __half22float2(region[s_off[2 * ROUND + p] + cpair]);
                float2 dq = __half22float2(region[s_off[3 * ROUND + p] + cpair]);
                val[p * 17 + 2 * cpair]     = w0 * a.x + w1 * bq.x + w2 * cq.x + w3 * dq.x;
                val[p * 17 + 2 * cpair + 1] = w0 * a.y + w1 * bq.y + w2 * cq.y + w3 * dq.y;
            }
        } else {
            const float* mc0 = m + (size_t)(b * C + coff + 2 * cpair) * (HH * WW);
            const float* mc1 = mc0 + HH * WW;
#pragma unroll
            for (int pass = 0; pass < 4; pass++) {
                int p = pass * 64 + (w << 2) + (lane >> 3);
                float ax = 0.0f, ay = 0.0f;
#pragma unroll
                for (int t = 0; t < 4; t++) {
                    int o = s_off[t * ROUND + p];
                    float wt = s_wt[t * ROUND + p];
                    ax += wt * mc0[o];
                    ay += wt * mc1[o];
                }
                val[p * 17 + 2 * cpair]     = ax;
                val[p * 17 + 2 * cpair + 1] = ay;
            }
        }
        __syncthreads();

        // --- stage round r+1 (overlaps the write phase; touches only s_wt/s_off)
        if (r + 1 < NROUNDS && tid < ROUND) {
            int idx = b * NN + n0 + ROUND + tid;
            int x0, x1, y0, y1; float wx, wy;
            point_coords(g_grid0[idx], g_grid1[idx], x0, x1, y0, y1, wx, wy);
            s_wt[0 * ROUND + tid] = (1.0f - wy) * (1.0f - wx);
            s_wt[1 * ROUND + tid] = (1.0f - wy) * wx;
            s_wt[2 * ROUND + tid] = wy * (1.0f - wx);
            s_wt[3 * ROUND + tid] = wy * wx;
            if (use_smem) {
                s_off[0 * ROUND + tid] = ((y0 - by0) * RGW + (x0 - bx0)) * 8;
                s_off[1 * ROUND + tid] = ((y0 - by0) * RGW + (x1 - bx0)) * 8;
                s_off[2 * ROUND + tid] = ((y1 - by0) * RGW + (x0 - bx0)) * 8;
                s_off[3 * ROUND + tid] = ((y1 - by0) * RGW + (x1 - bx0)) * 8;
            } else {
                s_off[0 * ROUND + tid] = y0 * WW + x0;
                s_off[1 * ROUND + tid] = y0 * WW + x1;
                s_off[2 * ROUND + tid] = y1 * WW + x0;
                s_off[3 * ROUND + tid] = y1 * WW + x1;
            }
        }

        // --- write: warp w owns channel c0 + w, n coalesced ---
        float* op = out + ((size_t)(b * C_ALL + c0 + w)) * NN + n0;
#pragma unroll
        for (int i = 0; i < 8; i++)
            __stcs(&op[i * 32 + lane], val[(i * 32 + lane) * 17 + w]);
        __syncthreads();
    }
}

// ---------------------------------------------------------------------------
extern "C" void kernel_launch(void* const* d_in, const int* in_sizes, int n_in,
                              void* d_out, int out_size) {
    const float* x_loc  = (const float*)d_in[0];
    const float* x_feat = (const float*)d_in[1];
    const float* m0     = (const float*)d_in[2];
    const float* m1     = (const float*)d_in[3];
    const float* m2     = (const float*)d_in[4];
    const float* W1     = (const float*)d_in[5];
    const float* b1     = (const float*)d_in[6];
    const float* W2     = (const float*)d_in[7];
    const float* b2     = (const float*)d_in[8];
    const float* Wr     = (const float*)d_in[9];
    const float* br     = (const float*)d_in[10];
    float* out = (float*)d_out;

    cudaFuncSetAttribute(sample_kernel,
                         cudaFuncAttributeMaxDynamicSharedMemorySize, SMEM_BYTES);

    check_wr_kernel<<<1, 256>>>(Wr);
    base_grid_kernel<<<(BB * NN) / 256, 256>>>(x_loc, Wr, br);
    mlp_grid_kernel<<<(BB * NN) / 256, 256>>>(x_loc, x_feat, W1, b1, W2, b2, Wr);
    bbox_kernel<<<(BB * NN) / 256, 256>>>();
    sample_kernel<<<dim3(NSPLIT, NCHUNK, BB), 512, SMEM_BYTES>>>(m0, m1, m2, out);
}

// round 6
// speedup vs baseline: 1.6413x; 1.6389x over previous
#include <cuda_runtime.h>
#include <cuda_fp16.h>
#include <climits>

#define BB 4
#define NN 65536
#define HH 128
#define WW 128
#define C_ALL 448
#define NCH 56                 // 8-channel chunks
#define NSPLIT 32
#define PTS_PER_BLOCK (NN / NSPLIT)   // 2048
#define REGION_CAP 4900        // max bh*bw texels for smem path (70x70)
#define REGION_BYTES (REGION_CAP * 16)
#define SVALT_FLOATS (32 * 288)        // 32 warps x 8ch x 36
#define SMEM_TOTAL (2 * REGION_BYTES + SVALT_FLOATS * 4)   // 193664

// chunked NHWC fp16 scratch: [b][chunk56][y][x][8ch], 56 MB
__device__ __half g_t[(size_t)BB * NCH * HH * WW * 8];
__device__ float  g_grid0[BB * NN];
__device__ float  g_grid1[BB * NN];
__device__ int    g_bbox[BB][4];   // minx0, miny0, maxx1, maxy1
__device__ int    g_needs_mlp;

// ---------------------------------------------------------------------------
__device__ __forceinline__ void pc(float gx, float gy,
                                   int& x0, int& y0, float& wx, float& wy) {
    float ix = fminf(fmaxf(((gx + 1.0f) * 128.0f - 1.0f) * 0.5f, 0.0f), 127.0f);
    float iy = fminf(fmaxf(((gy + 1.0f) * 128.0f - 1.0f) * 0.5f, 0.0f), 127.0f);
    x0 = min((int)ix, 126);          // trunc == floor (ix >= 0); x1 = x0+1 always
    y0 = min((int)iy, 126);          // clamp reproduced by wx/wy hitting 1.0
    wx = ix - (float)x0;
    wy = iy - (float)y0;
}

// Block-wide bbox reduce; block = 512 threads, all same batch b.
__device__ __forceinline__ void bbox_reduce(int b, int x0, int y0) {
    __shared__ int sm[4][16];
    int mnx = __reduce_min_sync(0xffffffffu, x0);
    int mny = __reduce_min_sync(0xffffffffu, y0);
    int mxx = __reduce_max_sync(0xffffffffu, x0 + 1);
    int mxy = __reduce_max_sync(0xffffffffu, y0 + 1);
    int w = threadIdx.x >> 5;
    if ((threadIdx.x & 31) == 0) {
        sm[0][w] = mnx; sm[1][w] = mny; sm[2][w] = mxx; sm[3][w] = mxy;
    }
    __syncthreads();
    if (threadIdx.x == 0) {
        int a0 = sm[0][0], a1 = sm[1][0], a2 = sm[2][0], a3 = sm[3][0];
#pragma unroll
        for (int i = 1; i < 16; i++) {
            a0 = min(a0, sm[0][i]); a1 = min(a1, sm[1][i]);
            a2 = max(a2, sm[2][i]); a3 = max(a3, sm[3][i]);
        }
        atomicMin(&g_bbox[b][0], a0); atomicMin(&g_bbox[b][1], a1);
        atomicMax(&g_bbox[b][2], a2); atomicMax(&g_bbox[b][3], a3);
    }
}

// ---------------------------------------------------------------------------
__global__ void check_wr_kernel(const float* __restrict__ Wr) {
    if (threadIdx.x < BB) {
        g_bbox[threadIdx.x][0] = INT_MAX; g_bbox[threadIdx.x][1] = INT_MAX;
        g_bbox[threadIdx.x][2] = INT_MIN; g_bbox[threadIdx.x][3] = INT_MIN;
    }
    int nz = 0;
    for (int idx = threadIdx.x; idx < 2 * 131; idx += blockDim.x) {
        int k = idx % 131;
        if (k >= 3 && Wr[idx] != 0.0f) nz = 1;
    }
    int any = __syncthreads_or(nz);
    if (threadIdx.x == 0) g_needs_mlp = any;
}

// ---------------------------------------------------------------------------
// Base grid + fused bbox. 512 blocks x 512 threads; block spans one batch.
// ---------------------------------------------------------------------------
__global__ void __launch_bounds__(512) base_grid_kernel(
        const float* __restrict__ x_loc, const float* __restrict__ Wr,
        const float* __restrict__ br) {
    int idx = blockIdx.x * 512 + threadIdx.x;
    int b = idx >> 16, n = idx & (NN - 1);
    float x0v = x_loc[(b * 3 + 0) * NN + n];
    float x1v = x_loc[(b * 3 + 1) * NN + n];
    float x2v = x_loc[(b * 3 + 2) * NN + n];
    float g0 = br[0] + Wr[0] * x0v + Wr[1] * x1v + Wr[2] * x2v;
    float g1 = br[1] + Wr[131] * x0v + Wr[132] * x1v + Wr[133] * x2v;
    g_grid0[idx] = g0;
    g_grid1[idx] = g1;
    int x0, y0; float wx, wy;
    pc(g0, g1, x0, y0, wx, wy);
    bbox_reduce(b, x0, y0);
}

// ---------------------------------------------------------------------------
// Fallback MLP path (early-exits when Wr[:,3:]==0). Grows bbox when active;
// bbox only accumulates so the union is a safe superset.
// ---------------------------------------------------------------------------
__global__ void __launch_bounds__(512) mlp_grid_kernel(
        const float* __restrict__ x_loc, const float* __restrict__ x_feat,
        const float* __restrict__ W1, const float* __restrict__ b1,
        const float* __restrict__ W2, const float* __restrict__ b2,
        const float* __restrict__ Wr) {
    if (g_needs_mlp == 0) return;   // uniform branch
    int idx = blockIdx.x * 512 + threadIdx.x;
    int b = idx >> 16, n = idx & (NN - 1);

    float x[67];
    for (int k = 0; k < 3; k++)  x[k] = x_loc[(b * 3 + k) * NN + n];
    for (int k = 0; k < 64; k++) x[3 + k] = x_feat[(b * 64 + k) * NN + n];
    float h1[128];
    for (int j = 0; j < 128; j++) {
        float s = b1[j];
        for (int k = 0; k < 67; k++) s += W1[j * 67 + k] * x[k];
        h1[j] = fmaxf(s, 0.0f);
    }
    float g0 = 0.0f, g1 = 0.0f;
    for (int j = 0; j < 128; j++) {
        float s = b2[j];
        for (int k = 0; k < 128; k++) s += W2[j * 128 + k] * h1[k];
        s = fmaxf(s, 0.0f);
        g0 += Wr[3 + j] * s;
        g1 += Wr[131 + 3 + j] * s;
    }
    g0 += g_grid0[idx];
    g1 += g_grid1[idx];
    g_grid0[idx] = g0;
    g_grid1[idx] = g1;
    int x0, y0; float wx, wy;
    pc(g0, g1, x0, y0, wx, wy);
    bbox_reduce(b, x0, y0);
}

// ---------------------------------------------------------------------------
// bbox-gated transpose into chunked layout. grid (4, 14, 512), block (32,8).
// One block: one y, 32 x's, one 32-channel tile (= 4 chunks of 8).
// ---------------------------------------------------------------------------
__global__ void __launch_bounds__(256) transpose_kernel(
        const float* __restrict__ m0, const float* __restrict__ m1,
        const float* __restrict__ m2) {
    int b = blockIdx.z >> 7;
    int y = blockIdx.z & 127;
    int xt = blockIdx.x << 5;
    int bx0 = g_bbox[b][0], bx1 = g_bbox[b][2];
    int by0 = g_bbox[b][1], by1 = g_bbox[b][3];
    if (y < by0 || y > by1 || xt > bx1 || xt + 31 < bx0) return;

    int ct = blockIdx.y;                   // 14 tiles of 32 channels
    const float* m; int C, c0;
    if (ct < 2)      { m = m0; C = 64;  c0 = ct * 32; }
    else if (ct < 6) { m = m1; C = 128; c0 = (ct - 2) * 32; }
    else             { m = m2; C = 256; c0 = (ct - 6) * 32; }

    __shared__ float tile[32][33];
    int tx = threadIdx.x, ty = threadIdx.y;
    const float* src = m + ((size_t)(b * C + c0 + ty) * (HH * WW)) + y * WW + xt + tx;
#pragma unroll
    for (int i = 0; i < 4; i++)
        tile[ty + i * 8][tx] = src[(size_t)(i * 8) * (HH * WW)];
    __syncthreads();

    int w = ty, lane = tx;
    int cidx = lane & 15;                 // channel pair 0..15 (32 channels)
    int chunk_local = cidx >> 2;          // 0..3
    int c8 = (cidx & 3) * 2;              // 0,2,4,6 within chunk
#pragma unroll
    for (int p = 0; p < 2; p++) {
        int x = xt + w * 4 + p * 2 + (lane >> 4);
        __half2 h = __floats2half2_rn(tile[cidx * 2][x - xt], tile[cidx * 2 + 1][x - xt]);
        size_t dst = ((size_t)((b * NCH + ct * 4 + chunk_local) * (HH * WW)) + y * WW + x) * 8 + c8;
        *(__half2*)&g_t[dst] = h;
    }
}

// ---------------------------------------------------------------------------
// Sampler: 128 blocks (32 n-splits x 4 batches), 1024 threads, 1 block/SM.
// Coords/weights in registers (lane = point, reused across all 56 chunks).
// Double-buffered cp.async region prefetch from g_t; LDS.128 gathers;
// per-warp smem staging; float4 streaming writes. Global-gather fallback
// when the referenced region exceeds REGION_CAP texels.
// ---------------------------------------------------------------------------
__global__ void __launch_bounds__(1024, 1) sample_kernel(float* __restrict__ out) {
    int b = blockIdx.z;
    int nb = blockIdx.x * PTS_PER_BLOCK;
    extern __shared__ __align__(16) char smraw[];
    char* buf0 = smraw;
    char* buf1 = smraw + REGION_BYTES;
    float* svalt = (float*)(smraw + 2 * REGION_BYTES);

    int tid = threadIdx.x, lane = tid & 31, w = tid >> 5;
    int bx0 = g_bbox[b][0], by0 = g_bbox[b][1];
    int bw = g_bbox[b][2] - bx0 + 1;
    int bh = g_bbox[b][3] - by0 + 1;
    bool smem_path = (bw * bh) <= REGION_CAP;

    // this warp's 64 points, coords in registers
    int pb = nb + w * 64;
    float wt0[2], wt1[2], wt2[2], wt3[2];
    int ob[2];
#pragma unroll
    for (int it = 0; it < 2; it++) {
        int idx = b * NN + pb + it * 32 + lane;
        int x0, y0; float wx, wy;
        pc(g_grid0[idx], g_grid1[idx], x0, y0, wx, wy);
        wt0[it] = (1.0f - wy) * (1.0f - wx);
        wt1[it] = (1.0f - wy) * wx;
        wt2[it] = wy * (1.0f - wx);
        wt3[it] = wy * wx;
        ob[it] = smem_path ? ((y0 - by0) * bw + (x0 - bx0)) * 16
                           : (y0 * WW + x0) * 16;
    }
    int row2 = smem_path ? bw * 16 : WW * 16;
    const char* slab = (const char*)(g_t + (size_t)b * NCH * (HH * WW) * 8);
    float* svw = svalt + w * 288;   // [8 ch][36]

    if (smem_path) {
        // prefetch chunk 0 into buf0
        {
            const char* s0 = slab;
            for (int r = w; r < bh; r += 32) {
                const char* srow = s0 + ((size_t)(r + by0) * WW + bx0) * 16;
                char* drow = buf0 + (size_t)r * bw * 16;
                for (int dx = lane; dx < bw; dx += 32) {
                    unsigned sa = (unsigned)__cvta_generic_to_shared(drow + dx * 16);
                    asm volatile("cp.async.ca.shared.global [%0], [%1], 16;\n"
                                 :: "r"(sa), "l"(srow + dx * 16));
                }
            }
            asm volatile("cp.async.commit_group;\n");
        }
        for (int ch = 0; ch < NCH; ch++) {
            asm volatile("cp.async.wait_group 0;\n");   // prefetch(ch) landed
            __syncthreads();
            // prefetch(ch+1) into the other buffer (safe: last reads of that
            // buffer were for ch-1 and finished before the end-of-iter sync)
            if (ch + 1 < NCH) {
                const char* s1 = slab + (size_t)(ch + 1) * (HH * WW * 16);
                char* d = ((ch + 1) & 1) ? buf1 : buf0;
                for (int r = w; r < bh; r += 32) {
                    const char* srow = s1 + ((size_t)(r + by0) * WW + bx0) * 16;
                    char* drow = d + (size_t)r * bw * 16;
                    for (int dx = lane; dx < bw; dx += 32) {
                        unsigned sa = (unsigned)__cvta_generic_to_shared(drow + dx * 16);
                        asm volatile("cp.async.ca.shared.global [%0], [%1], 16;\n"
                                     :: "r"(sa), "l"(srow + dx * 16));
                    }
                }
                asm volatile("cp.async.commit_group;\n");
            }

            const char* rg = (ch & 1) ? buf1 : buf0;
#pragma unroll
            for (int it = 0; it < 2; it++) {
                int o = ob[it];
                uint4 u0 = *(const uint4*)(rg + o);
                uint4 u1 = *(const uint4*)(rg + o + 16);
                uint4 u2 = *(const uint4*)(rg + o + row2);
                uint4 u3 = *(const uint4*)(rg + o + row2 + 16);
                float w0 = wt0[it], w1 = wt1[it], w2 = wt2[it], w3 = wt3[it];
#pragma unroll
                for (int k = 0; k < 4; k++) {
                    float2 a  = __half22float2(((const __half2*)&u0)[k]);
                    float2 b2 = __half22float2(((const __half2*)&u1)[k]);
                    float2 c2 = __half22float2(((const __half2*)&u2)[k]);
                    float2 d2 = __half22float2(((const __half2*)&u3)[k]);
                    svw[(2 * k) * 36 + lane]     = w0 * a.x + w1 * b2.x + w2 * c2.x + w3 * d2.x;
                    svw[(2 * k + 1) * 36 + lane] = w0 * a.y + w1 * b2.y + w2 * c2.y + w3 * d2.y;
                }
                __syncwarp();
                int n0 = pb + it * 32;
#pragma unroll
                for (int j = 0; j < 2; j++) {
                    int c = j * 4 + (lane >> 3);
                    int nq = lane & 7;
                    float4 v = *(float4*)&svw[c * 36 + nq * 4];
                    __stcs((float4*)(out + (((size_t)(b * C_ALL + ch * 8 + c)) << 16) + n0 + nq * 4), v);
                }
                __syncwarp();
            }
            __syncthreads();
        }
    } else {
        // general fallback: gather straight from g_t (correct, uncoalesced)
        for (int ch = 0; ch < NCH; ch++) {
            const char* gs = slab + (size_t)ch * (HH * WW * 16);
#pragma unroll
            for (int it = 0; it < 2; it++) {
                int o = ob[it];
                uint4 u0 = __ldg((const uint4*)(gs + o));
                uint4 u1 = __ldg((const uint4*)(gs + o + 16));
                uint4 u2 = __ldg((const uint4*)(gs + o + row2));
                uint4 u3 = __ldg((const uint4*)(gs + o + row2 + 16));
                float w0 = wt0[it], w1 = wt1[it], w2 = wt2[it], w3 = wt3[it];
#pragma unroll
                for (int k = 0; k < 4; k++) {
                    float2 a  = __half22float2(((const __half2*)&u0)[k]);
                    float2 b2 = __half22float2(((const __half2*)&u1)[k]);
                    float2 c2 = __half22float2(((const __half2*)&u2)[k]);
                    float2 d2 = __half22float2(((const __half2*)&u3)[k]);
                    svw[(2 * k) * 36 + lane]     = w0 * a.x + w1 * b2.x + w2 * c2.x + w3 * d2.x;
                    svw[(2 * k + 1) * 36 + lane] = w0 * a.y + w1 * b2.y + w2 * c2.y + w3 * d2.y;
                }
                __syncwarp();
                int n0 = pb + it * 32;
#pragma unroll
                for (int j = 0; j < 2; j++) {
                    int c = j * 4 + (lane >> 3);
                    int nq = lane & 7;
                    float4 v = *(float4*)&svw[c * 36 + nq * 4];
                    __stcs((float4*)(out + (((size_t)(b * C_ALL + ch * 8 + c)) << 16) + n0 + nq * 4), v);
                }
                __syncwarp();
            }
        }
    }
}

// ---------------------------------------------------------------------------
extern "C" void kernel_launch(void* const* d_in, const int* in_sizes, int n_in,
                              void* d_out, int out_size) {
    const float* x_loc  = (const float*)d_in[0];
    const float* x_feat = (const float*)d_in[1];
    const float* m0     = (const float*)d_in[2];
    const float* m1     = (const float*)d_in[3];
    const float* m2     = (const float*)d_in[4];
    const float* W1     = (const float*)d_in[5];
    const float* b1     = (const float*)d_in[6];
    const float* W2     = (const float*)d_in[7];
    const float* b2     = (const float*)d_in[8];
    const float* Wr     = (const float*)d_in[9];
    const float* br     = (const float*)d_in[10];
    float* out = (float*)d_out;

    static int smem_set = 0;
    if (!smem_set) {
        cudaFuncSetAttribute(sample_kernel,
                             cudaFuncAttributeMaxDynamicSharedMemorySize, SMEM_TOTAL);
        smem_set = 1;
    }

    check_wr_kernel<<<1, 256>>>(Wr);
    base_grid_kernel<<<512, 512>>>(x_loc, Wr, br);
    mlp_grid_kernel<<<512, 512>>>(x_loc, x_feat, W1, b1, W2, b2, Wr);
    transpose_kernel<<<dim3(4, 14, 512), dim3(32, 8)>>>(m0, m1, m2);
    sample_kernel<<<dim3(NSPLIT, 1, BB), 1024, SMEM_TOTAL>>>(out);
}

// round 7
// speedup vs baseline: 2.2069x; 1.3446x over previous
#include <cuda_runtime.h>
#include <cuda_fp16.h>
#include <climits>

#define BB 4
#define NN 65536
#define HH 128
#define WW 128
#define C_ALL 448   // 64 + 128 + 256

// fused NHWC fp16 scratch [b][y][x][448], 56 MB
__device__ __half g_t[(size_t)BB * HH * WW * C_ALL];
__device__ float  g_grid0[BB * NN];
__device__ float  g_grid1[BB * NN];
__device__ int    g_bbox[BB][4];   // minx0, miny0, maxx1, maxy1
__device__ int    g_needs_mlp;

// ---------------------------------------------------------------------------
__device__ __forceinline__ void point_coords(float gx, float gy,
                                             int& x0, int& x1, int& y0, int& y1,
                                             float& wx, float& wy) {
    float ix = ((gx + 1.0f) * 128.0f - 1.0f) * 0.5f;
    float iy = ((gy + 1.0f) * 128.0f - 1.0f) * 0.5f;
    ix = fminf(fmaxf(ix, 0.0f), 127.0f);
    iy = fminf(fmaxf(iy, 0.0f), 127.0f);
    float fx0 = floorf(ix), fy0 = floorf(iy);
    wx = ix - fx0; wy = iy - fy0;
    x0 = (int)fx0; y0 = (int)fy0;
    x1 = min(x0 + 1, 127); y1 = min(y0 + 1, 127);
}

// Block-wide bbox reduce; 512-thread block, all threads same batch b.
__device__ __forceinline__ void bbox_reduce(int b, int x0, int y0,
                                            int x1, int y1) {
    __shared__ int sm[4][16];
    int mnx = __reduce_min_sync(0xffffffffu, x0);
    int mny = __reduce_min_sync(0xffffffffu, y0);
    int mxx = __reduce_max_sync(0xffffffffu, x1);
    int mxy = __reduce_max_sync(0xffffffffu, y1);
    int w = threadIdx.x >> 5;
    if ((threadIdx.x & 31) == 0) {
        sm[0][w] = mnx; sm[1][w] = mny; sm[2][w] = mxx; sm[3][w] = mxy;
    }
    __syncthreads();
    if (threadIdx.x == 0) {
        int a0 = sm[0][0], a1 = sm[1][0], a2 = sm[2][0], a3 = sm[3][0];
#pragma unroll
        for (int i = 1; i < 16; i++) {
            a0 = min(a0, sm[0][i]); a1 = min(a1, sm[1][i]);
            a2 = max(a2, sm[2][i]); a3 = max(a3, sm[3][i]);
        }
        atomicMin(&g_bbox[b][0], a0); atomicMin(&g_bbox[b][1], a1);
        atomicMax(&g_bbox[b][2], a2); atomicMax(&g_bbox[b][3], a3);
    }
}

// ---------------------------------------------------------------------------
__global__ void check_wr_kernel(const float* __restrict__ Wr) {
    if (threadIdx.x < BB) {
        g_bbox[threadIdx.x][0] = INT_MAX; g_bbox[threadIdx.x][1] = INT_MAX;
        g_bbox[threadIdx.x][2] = INT_MIN; g_bbox[threadIdx.x][3] = INT_MIN;
    }
    int nz = 0;
    for (int idx = threadIdx.x; idx < 2 * 131; idx += blockDim.x) {
        int k = idx % 131;
        if (k >= 3 && Wr[idx] != 0.0f) nz = 1;
    }
    int any = __syncthreads_or(nz);
    if (threadIdx.x == 0) g_needs_mlp = any;
}

// ---------------------------------------------------------------------------
// Base grid + fused bbox. 512 blocks x 512 threads; block spans one batch.
// ---------------------------------------------------------------------------
__global__ void __launch_bounds__(512) base_grid_kernel(
        const float* __restrict__ x_loc, const float* __restrict__ Wr,
        const float* __restrict__ br) {
    int idx = blockIdx.x * 512 + threadIdx.x;
    int b = idx >> 16, n = idx & (NN - 1);
    float x0v = x_loc[(b * 3 + 0) * NN + n];
    float x1v = x_loc[(b * 3 + 1) * NN + n];
    float x2v = x_loc[(b * 3 + 2) * NN + n];
    float g0 = br[0] + Wr[0] * x0v + Wr[1] * x1v + Wr[2] * x2v;
    float g1 = br[1] + Wr[131] * x0v + Wr[132] * x1v + Wr[133] * x2v;
    g_grid0[idx] = g0;
    g_grid1[idx] = g1;
    int x0, x1, y0, y1; float wx, wy;
    point_coords(g0, g1, x0, x1, y0, y1, wx, wy);
    bbox_reduce(b, x0, y0, x1, y1);
}

// ---------------------------------------------------------------------------
// Fallback MLP path (early-exits when Wr[:,3:]==0, as in this dataset).
// When active it grows the bbox; bbox only accumulates so union is safe.
// ---------------------------------------------------------------------------
__global__ void __launch_bounds__(512) mlp_grid_kernel(
        const float* __restrict__ x_loc, const float* __restrict__ x_feat,
        const float* __restrict__ W1, const float* __restrict__ b1,
        const float* __restrict__ W2, const float* __restrict__ b2,
        const float* __restrict__ Wr) {
    if (g_needs_mlp == 0) return;   // uniform branch
    int idx = blockIdx.x * 512 + threadIdx.x;
    int b = idx >> 16, n = idx & (NN - 1);

    float x[67];
    for (int k = 0; k < 3; k++)  x[k] = x_loc[(b * 3 + k) * NN + n];
    for (int k = 0; k < 64; k++) x[3 + k] = x_feat[(b * 64 + k) * NN + n];
    float h1[128];
    for (int j = 0; j < 128; j++) {
        float s = b1[j];
        for (int k = 0; k < 67; k++) s += W1[j * 67 + k] * x[k];
        h1[j] = fmaxf(s, 0.0f);
    }
    float g0 = 0.0f, g1 = 0.0f;
    for (int j = 0; j < 128; j++) {
        float s = b2[j];
        for (int k = 0; k < 128; k++) s += W2[j * 128 + k] * h1[k];
        s = fmaxf(s, 0.0f);
        g0 += Wr[3 + j] * s;
        g1 += Wr[131 + 3 + j] * s;
    }
    g0 += g_grid0[idx];
    g1 += g_grid1[idx];
    g_grid0[idx] = g0;
    g_grid1[idx] = g1;
    int x0, x1, y0, y1; float wx, wy;
    point_coords(g0, g1, x0, x1, y0, y1, wx, wy);
    bbox_reduce(b, x0, y0, x1, y1);
}

// ---------------------------------------------------------------------------
// bbox-gated transpose to flat NHWC fp16. grid (4, 7, 512), block (32,8).
// One block: one y, 32 x's, one 64-channel tile. Warp stores 64 contiguous
// fp16 channels (128 B) per texel -> fully coalesced.
// ---------------------------------------------------------------------------
__global__ void __launch_bounds__(256) transpose_kernel(
        const float* __restrict__ m0, const float* __restrict__ m1,
        const float* __restrict__ m2) {
    int b = blockIdx.z >> 7;
    int y = blockIdx.z & 127;
    int xt = blockIdx.x << 5;
    int bx0 = g_bbox[b][0], bx1 = g_bbox[b][2];
    int by0 = g_bbox[b][1], by1 = g_bbox[b][3];
    if (y < by0 || y > by1 || xt > bx1 || xt + 31 < bx0) return;

    int ct = blockIdx.y;                   // 7 tiles of 64 channels
    const float* m; int C, c0, coff;
    if (ct == 0)      { m = m0; C = 64;  c0 = 0;             coff = 0; }
    else if (ct < 3)  { m = m1; C = 128; c0 = (ct - 1) * 64; coff = 64 + c0; }
    else              { m = m2; C = 256; c0 = (ct - 3) * 64; coff = 192 + c0; }

    __shared__ float tile[64][33];
    int tx = threadIdx.x, ty = threadIdx.y;
    const float* src = m + ((size_t)(b * C + c0 + ty) * (HH * WW)) + y * WW + xt + tx;
#pragma unroll
    for (int i = 0; i < 8; i++)
        tile[ty + i * 8][tx] = src[(size_t)(i * 8) * (HH * WW)];
    __syncthreads();

    // warp w handles x = xt + 4w .. 4w+3; lane = channel pair -> 128 B store
    int w = ty, lane = tx;
#pragma unroll
    for (int xi = 0; xi < 4; xi++) {
        int x = (w << 2) + xi;
        __half2 h = __floats2half2_rn(tile[2 * lane][x], tile[2 * lane + 1][x]);
        *(__half2*)&g_t[((size_t)((b * HH + y) * WW + xt + x)) * C_ALL + coff + 2 * lane] = h;
    }
}

// ---------------------------------------------------------------------------
// Bilinear gather + channel transpose (proven R3 design, L2-bound).
// 32 points/block, 256 threads. 7 chunks of 64 channels; half2 row reads
// (one 128 B transaction per texel row); stride-65 smem staging; streaming
// coalesced writes.
// ---------------------------------------------------------------------------
__global__ void __launch_bounds__(256) sample_kernel(float* __restrict__ out) {
    __shared__ float s_w[4][32];
    __shared__ int   s_base[4][32];
    __shared__ float val[32 * 65];

    int b   = blockIdx.y;
    int n0  = blockIdx.x << 5;
    int tid = threadIdx.x;
    int lane = tid & 31, w = tid >> 5;

    if (tid < 32) {
        int idx = b * NN + n0 + tid;
        int x0, x1, y0, y1; float wx, wy;
        point_coords(g_grid0[idx], g_grid1[idx], x0, x1, y0, y1, wx, wy);
        s_w[0][tid] = (1.0f - wy) * (1.0f - wx);
        s_w[1][tid] = (1.0f - wy) * wx;
        s_w[2][tid] = wy * (1.0f - wx);
        s_w[3][tid] = wy * wx;
        int r0 = (b * HH + y0) * WW;
        int r1 = (b * HH + y1) * WW;
        s_base[0][tid] = (r0 + x0) * C_ALL;
        s_base[1][tid] = (r0 + x1) * C_ALL;
        s_base[2][tid] = (r1 + x0) * C_ALL;
        s_base[3][tid] = (r1 + x1) * C_ALL;
    }
    __syncthreads();

#pragma unroll
    for (int chunk = 0; chunk < 7; chunk++) {
        int c0 = chunk * 64;
#pragma unroll
        for (int i = 0; i < 4; i++) {
            int p = (w << 2) + i;
            float w00 = s_w[0][p], w01 = s_w[1][p], w10 = s_w[2][p], w11 = s_w[3][p];
            int b0 = s_base[0][p], b1v = s_base[1][p], b2v = s_base[2][p], b3v = s_base[3][p];
            int cc = c0 + (lane << 1);
            float2 a  = __half22float2(*(const __half2*)&g_t[b0  + cc]);
            float2 bq = __half22float2(*(const __half2*)&g_t[b1v + cc]);
            float2 cq = __half22float2(*(const __half2*)&g_t[b2v + cc]);
            float2 dq = __half22float2(*(const __half2*)&g_t[b3v + cc]);
            float2 r;
            r.x = w00 * a.x + w01 * bq.x + w10 * cq.x + w11 * dq.x;
            r.y = w00 * a.y + w01 * bq.y + w10 * cq.y + w11 * dq.y;
            val[p * 65 + (lane << 1)]     = r.x;
            val[p * 65 + (lane << 1) + 1] = r.y;
        }
        __syncthreads();
        float* outp = out + ((size_t)(b * C_ALL + c0 + w * 8)) * NN + n0 + lane;
#pragma unroll
        for (int j = 0; j < 8; j++)
            __stcs(&outp[(size_t)j * NN], val[lane * 65 + w * 8 + j]);
        __syncthreads();
    }
}

// ---------------------------------------------------------------------------
extern "C" void kernel_launch(void* const* d_in, const int* in_sizes, int n_in,
                              void* d_out, int out_size) {
    const float* x_loc  = (const float*)d_in[0];
    const float* x_feat = (const float*)d_in[1];
    const float* m0     = (const float*)d_in[2];
    const float* m1     = (const float*)d_in[3];
    const float* m2     = (const float*)d_in[4];
    const float* W1     = (const float*)d_in[5];
    const float* b1     = (const float*)d_in[6];
    const float* W2     = (const float*)d_in[7];
    const float* b2     = (const float*)d_in[8];
    const float* Wr     = (const float*)d_in[9];
    const float* br     = (const float*)d_in[10];
    float* out = (float*)d_out;

    check_wr_kernel<<<1, 256>>>(Wr);
    base_grid_kernel<<<512, 512>>>(x_loc, Wr, br);
    mlp_grid_kernel<<<512, 512>>>(x_loc, x_feat, W1, b1, W2, b2, Wr);
    transpose_kernel<<<dim3(4, 7, 512), dim3(32, 8)>>>(m0, m1, m2);
    sample_kernel<<<dim3(NN / 32, BB), 256>>>(out);
}

// round 8
// speedup vs baseline: 2.6020x; 1.1790x over previous
#include <cuda_runtime.h>
#include <cuda_fp16.h>
#include <climits>

#define BB 4
#define NN 65536
#define HH 128
#define WW 128
#define C_ALL 448   // 64 + 128 + 256

// fused NHWC fp16 scratch [b][y][x][448], 56 MB
__device__ __half g_t[(size_t)BB * HH * WW * C_ALL];
__device__ float  g_grid0[BB * NN];
__device__ float  g_grid1[BB * NN];
__device__ int    g_bbox[BB][4];   // minx0, miny0, maxx1, maxy1
__device__ int    g_needs_mlp;

// ---------------------------------------------------------------------------
__device__ __forceinline__ void point_coords(float gx, float gy,
                                             int& x0, int& x1, int& y0, int& y1,
                                             float& wx, float& wy) {
    float ix = ((gx + 1.0f) * 128.0f - 1.0f) * 0.5f;
    float iy = ((gy + 1.0f) * 128.0f - 1.0f) * 0.5f;
    ix = fminf(fmaxf(ix, 0.0f), 127.0f);
    iy = fminf(fmaxf(iy, 0.0f), 127.0f);
    float fx0 = floorf(ix), fy0 = floorf(iy);
    wx = ix - fx0; wy = iy - fy0;
    x0 = (int)fx0; y0 = (int)fy0;
    x1 = min(x0 + 1, 127); y1 = min(y0 + 1, 127);
}

// Block-wide bbox reduce; 512-thread block, all threads same batch b.
__device__ __forceinline__ void bbox_reduce(int b, int x0, int y0,
                                            int x1, int y1) {
    __shared__ int sm[4][16];
    int mnx = __reduce_min_sync(0xffffffffu, x0);
    int mny = __reduce_min_sync(0xffffffffu, y0);
    int mxx = __reduce_max_sync(0xffffffffu, x1);
    int mxy = __reduce_max_sync(0xffffffffu, y1);
    int w = threadIdx.x >> 5;
    if ((threadIdx.x & 31) == 0) {
        sm[0][w] = mnx; sm[1][w] = mny; sm[2][w] = mxx; sm[3][w] = mxy;
    }
    __syncthreads();
    if (threadIdx.x == 0) {
        int a0 = sm[0][0], a1 = sm[1][0], a2 = sm[2][0], a3 = sm[3][0];
#pragma unroll
        for (int i = 1; i < 16; i++) {
            a0 = min(a0, sm[0][i]); a1 = min(a1, sm[1][i]);
            a2 = max(a2, sm[2][i]); a3 = max(a3, sm[3][i]);
        }
        atomicMin(&g_bbox[b][0], a0); atomicMin(&g_bbox[b][1], a1);
        atomicMax(&g_bbox[b][2], a2); atomicMax(&g_bbox[b][3], a3);
    }
}

// ---------------------------------------------------------------------------
__global__ void check_wr_kernel(const float* __restrict__ Wr) {
    if (threadIdx.x < BB) {
        g_bbox[threadIdx.x][0] = INT_MAX; g_bbox[threadIdx.x][1] = INT_MAX;
        g_bbox[threadIdx.x][2] = INT_MIN; g_bbox[threadIdx.x][3] = INT_MIN;
    }
    int nz = 0;
    for (int idx = threadIdx.x; idx < 2 * 131; idx += blockDim.x) {
        int k = idx % 131;
        if (k >= 3 && Wr[idx] != 0.0f) nz = 1;
    }
    int any = __syncthreads_or(nz);
    if (threadIdx.x == 0) g_needs_mlp = any;
}

// ---------------------------------------------------------------------------
// Base grid + fused bbox. 512 blocks x 512 threads; block spans one batch.
// ---------------------------------------------------------------------------
__global__ void __launch_bounds__(512) base_grid_kernel(
        const float* __restrict__ x_loc, const float* __restrict__ Wr,
        const float* __restrict__ br) {
    int idx = blockIdx.x * 512 + threadIdx.x;
    int b = idx >> 16, n = idx & (NN - 1);
    float x0v = x_loc[(b * 3 + 0) * NN + n];
    float x1v = x_loc[(b * 3 + 1) * NN + n];
    float x2v = x_loc[(b * 3 + 2) * NN + n];
    float g0 = br[0] + Wr[0] * x0v + Wr[1] * x1v + Wr[2] * x2v;
    float g1 = br[1] + Wr[131] * x0v + Wr[132] * x1v + Wr[133] * x2v;
    g_grid0[idx] = g0;
    g_grid1[idx] = g1;
    int x0, x1, y0, y1; float wx, wy;
    point_coords(g0, g1, x0, x1, y0, y1, wx, wy);
    bbox_reduce(b, x0, y0, x1, y1);
}

// ---------------------------------------------------------------------------
// Fallback MLP path (early-exits when Wr[:,3:]==0, as in this dataset).
// When active it grows the bbox; bbox only accumulates so union is safe.
// ---------------------------------------------------------------------------
__global__ void __launch_bounds__(512) mlp_grid_kernel(
        const float* __restrict__ x_loc, const float* __restrict__ x_feat,
        const float* __restrict__ W1, const float* __restrict__ b1,
        const float* __restrict__ W2, const float* __restrict__ b2,
        const float* __restrict__ Wr) {
    if (g_needs_mlp == 0) return;   // uniform branch
    int idx = blockIdx.x * 512 + threadIdx.x;
    int b = idx >> 16, n = idx & (NN - 1);

    float x[67];
    for (int k = 0; k < 3; k++)  x[k] = x_loc[(b * 3 + k) * NN + n];
    for (int k = 0; k < 64; k++) x[3 + k] = x_feat[(b * 64 + k) * NN + n];
    float h1[128];
    for (int j = 0; j < 128; j++) {
        float s = b1[j];
        for (int k = 0; k < 67; k++) s += W1[j * 67 + k] * x[k];
        h1[j] = fmaxf(s, 0.0f);
    }
    float g0 = 0.0f, g1 = 0.0f;
    for (int j = 0; j < 128; j++) {
        float s = b2[j];
        for (int k = 0; k < 128; k++) s += W2[j * 128 + k] * h1[k];
        s = fmaxf(s, 0.0f);
        g0 += Wr[3 + j] * s;
        g1 += Wr[131 + 3 + j] * s;
    }
    g0 += g_grid0[idx];
    g1 += g_grid1[idx];
    g_grid0[idx] = g0;
    g_grid1[idx] = g1;
    int x0, x1, y0, y1; float wx, wy;
    point_coords(g0, g1, x0, x1, y0, y1, wx, wy);
    bbox_reduce(b, x0, y0, x1, y1);
}

// ---------------------------------------------------------------------------
// bbox-gated transpose to flat NHWC fp16. grid (4, 7, 256), block (32,8).
// One block: TWO y rows, 32 x's, one 64-channel tile (16 in-flight loads
// per thread for latency hiding). Warp stores 64 contiguous fp16 channels
// (128 B) per texel -> fully coalesced.
// ---------------------------------------------------------------------------
__global__ void __launch_bounds__(256) transpose_kernel(
        const float* __restrict__ m0, const float* __restrict__ m1,
        const float* __restrict__ m2) {
    int b  = blockIdx.z >> 6;
    int yb = (blockIdx.z & 63) << 1;
    int xt = blockIdx.x << 5;
    int bx0 = g_bbox[b][0], bx1 = g_bbox[b][2];
    int by0 = g_bbox[b][1], by1 = g_bbox[b][3];
    if (yb + 1 < by0 || yb > by1 || xt > bx1 || xt + 31 < bx0) return;

    int ct = blockIdx.y;                   // 7 tiles of 64 channels
    const float* m; int C, c0, coff;
    if (ct == 0)      { m = m0; C = 64;  c0 = 0;             coff = 0; }
    else if (ct < 3)  { m = m1; C = 128; c0 = (ct - 1) * 64; coff = 64 + c0; }
    else              { m = m2; C = 256; c0 = (ct - 3) * 64; coff = 192 + c0; }

    __shared__ float tile[2][64][33];
    int tx = threadIdx.x, ty = threadIdx.y;
    const float* src = m + ((size_t)(b * C + c0 + ty) * (HH * WW)) + yb * WW + xt + tx;
#pragma unroll
    for (int yy = 0; yy < 2; yy++)
#pragma unroll
        for (int i = 0; i < 8; i++)
            tile[yy][ty + i * 8][tx] = src[(size_t)(i * 8) * (HH * WW) + yy * WW];
    __syncthreads();

    // warp w handles x = xt + 4w .. 4w+3; lane = channel pair -> 128 B store
    int w = ty, lane = tx;
#pragma unroll
    for (int yy = 0; yy < 2; yy++)
#pragma unroll
        for (int xi = 0; xi < 4; xi++) {
            int x = (w << 2) + xi;
            __half2 h = __floats2half2_rn(tile[yy][2 * lane][x], tile[yy][2 * lane + 1][x]);
            *(__half2*)&g_t[((size_t)((b * HH + yb + yy) * WW + xt + x)) * C_ALL + coff + 2 * lane] = h;
        }
}

// ---------------------------------------------------------------------------
// Bilinear gather + channel transpose. 64 points/block, 512 threads.
// Warp handles 4 points: lane>>3 = point-sub, lane&7 = channel octet.
// Each lane loads float4 (8 fp16) per texel row -> LDG.128, 512 B/warp,
// 4x fewer/wider loads than R7. Stride-65 staging (phase-2 conflict-free);
// streaming coalesced writes.
// ---------------------------------------------------------------------------
__global__ void __launch_bounds__(512) sample_kernel(float* __restrict__ out) {
    __shared__ float s_w[4][64];
    __shared__ int   s_base[4][64];
    __shared__ float val[64 * 65];

    int b   = blockIdx.y;
    int n0  = blockIdx.x << 6;
    int tid = threadIdx.x;
    int lane = tid & 31, w = tid >> 5;

    if (tid < 64) {
        int idx = b * NN + n0 + tid;
        int x0, x1, y0, y1; float wx, wy;
        point_coords(g_grid0[idx], g_grid1[idx], x0, x1, y0, y1, wx, wy);
        s_w[0][tid] = (1.0f - wy) * (1.0f - wx);
        s_w[1][tid] = (1.0f - wy) * wx;
        s_w[2][tid] = wy * (1.0f - wx);
        s_w[3][tid] = wy * wx;
        int r0 = (b * HH + y0) * WW;
        int r1 = (b * HH + y1) * WW;
        s_base[0][tid] = (r0 + x0) * C_ALL;
        s_base[1][tid] = (r0 + x1) * C_ALL;
        s_base[2][tid] = (r1 + x0) * C_ALL;
        s_base[3][tid] = (r1 + x1) * C_ALL;
    }
    __syncthreads();

    int p   = (w << 2) + (lane >> 3);   // this lane's point (0..63)
    int oct = lane & 7;                 // channel octet within 64-ch chunk

#pragma unroll
    for (int chunk = 0; chunk < 7; chunk++) {
        int c0 = chunk * 64;
        int cc = c0 + (oct << 3);
        float r[8] = {0.f, 0.f, 0.f, 0.f, 0.f, 0.f, 0.f, 0.f};
#pragma unroll
        for (int t = 0; t < 4; t++) {
            float wt = s_w[t][p];
            uint4 u = *(const uint4*)&g_t[s_base[t][p] + cc];
#pragma unroll
            for (int k = 0; k < 4; k++) {
                float2 f = __half22float2(((const __half2*)&u)[k]);
                r[2 * k]     += wt * f.x;
                r[2 * k + 1] += wt * f.y;
            }
        }
        float* vp = &val[p * 65 + (oct << 3)];
#pragma unroll
        for (int k = 0; k < 8; k++) vp[k] = r[k];
        __syncthreads();

        // write: warp w owns channels c0+4w..4w+3, 64 n's each (coalesced)
#pragma unroll
        for (int j = 0; j < 4; j++) {
            float* outp = out + ((size_t)(b * C_ALL + c0 + (w << 2) + j)) * NN + n0;
#pragma unroll
            for (int it = 0; it < 2; it++) {
                int n = it * 32 + lane;
                __stcs(&outp[n], val[n * 65 + (w << 2) + j]);
            }
        }
        __syncthreads();
    }
}

// ---------------------------------------------------------------------------
extern "C" void kernel_launch(void* const* d_in, const int* in_sizes, int n_in,
                              void* d_out, int out_size) {
    const float* x_loc  = (const float*)d_in[0];
    const float* x_feat = (const float*)d_in[1];
    const float* m0     = (const float*)d_in[2];
    const float* m1     = (const float*)d_in[3];
    const float* m2     = (const float*)d_in[4];
    const float* W1     = (const float*)d_in[5];
    const float* b1     = (const float*)d_in[6];
    const float* W2     = (const float*)d_in[7];
    const float* b2     = (const float*)d_in[8];
    const float* Wr     = (const float*)d_in[9];
    const float* br     = (const float*)d_in[10];
    float* out = (float*)d_out;

    check_wr_kernel<<<1, 256>>>(Wr);
    base_grid_kernel<<<512, 512>>>(x_loc, Wr, br);
    mlp_grid_kernel<<<512, 512>>>(x_loc, x_feat, W1, b1, W2, b2, Wr);
    transpose_kernel<<<dim3(4, 7, 256), dim3(32, 8)>>>(m0, m1, m2);
    sample_kernel<<<dim3(NN / 64, BB), 512>>>(out);
}

// round 9
// speedup vs baseline: 2.6880x; 1.0331x over previous
#include <cuda_runtime.h>
#include <cuda_fp16.h>
#include <climits>

#define BB 4
#define NN 65536
#define HH 128
#define WW 128
#define C_ALL 448   // 64 + 128 + 256

// fused NHWC fp16 scratch [b][y][x][448], 56 MB
__device__ __half g_t[(size_t)BB * HH * WW * C_ALL];
__device__ float  g_grid0[BB * NN];
__device__ float  g_grid1[BB * NN];
__device__ int    g_bbox[BB][4];   // minx0, miny0, maxx1, maxy1
__device__ int    g_needs_mlp;

// ---------------------------------------------------------------------------
__device__ __forceinline__ void point_coords(float gx, float gy,
                                             int& x0, int& x1, int& y0, int& y1,
                                             float& wx, float& wy) {
    float ix = ((gx + 1.0f) * 128.0f - 1.0f) * 0.5f;
    float iy = ((gy + 1.0f) * 128.0f - 1.0f) * 0.5f;
    ix = fminf(fmaxf(ix, 0.0f), 127.0f);
    iy = fminf(fmaxf(iy, 0.0f), 127.0f);
    float fx0 = floorf(ix), fy0 = floorf(iy);
    wx = ix - fx0; wy = iy - fy0;
    x0 = (int)fx0; y0 = (int)fy0;
    x1 = min(x0 + 1, 127); y1 = min(y0 + 1, 127);
}

// Block-wide bbox reduce; 512-thread block, all threads same batch b.
__device__ __forceinline__ void bbox_reduce(int b, int x0, int y0,
                                            int x1, int y1) {
    __shared__ int sm[4][16];
    int mnx = __reduce_min_sync(0xffffffffu, x0);
    int mny = __reduce_min_sync(0xffffffffu, y0);
    int mxx = __reduce_max_sync(0xffffffffu, x1);
    int mxy = __reduce_max_sync(0xffffffffu, y1);
    int w = threadIdx.x >> 5;
    if ((threadIdx.x & 31) == 0) {
        sm[0][w] = mnx; sm[1][w] = mny; sm[2][w] = mxx; sm[3][w] = mxy;
    }
    __syncthreads();
    if (threadIdx.x == 0) {
        int a0 = sm[0][0], a1 = sm[1][0], a2 = sm[2][0], a3 = sm[3][0];
#pragma unroll
        for (int i = 1; i < 16; i++) {
            a0 = min(a0, sm[0][i]); a1 = min(a1, sm[1][i]);
            a2 = max(a2, sm[2][i]); a3 = max(a3, sm[3][i]);
        }
        atomicMin(&g_bbox[b][0], a0); atomicMin(&g_bbox[b][1], a1);
        atomicMax(&g_bbox[b][2], a2); atomicMax(&g_bbox[b][3], a3);
    }
}

// ---------------------------------------------------------------------------
__global__ void check_wr_kernel(const float* __restrict__ Wr) {
    if (threadIdx.x < BB) {
        g_bbox[threadIdx.x][0] = INT_MAX; g_bbox[threadIdx.x][1] = INT_MAX;
        g_bbox[threadIdx.x][2] = INT_MIN; g_bbox[threadIdx.x][3] = INT_MIN;
    }
    int nz = 0;
    for (int idx = threadIdx.x; idx < 2 * 131; idx += blockDim.x) {
        int k = idx % 131;
        if (k >= 3 && Wr[idx] != 0.0f) nz = 1;
    }
    int any = __syncthreads_or(nz);
    if (threadIdx.x == 0) g_needs_mlp = any;
}

// ---------------------------------------------------------------------------
// Base grid + fused bbox. 512 blocks x 512 threads; block spans one batch.
// ---------------------------------------------------------------------------
__global__ void __launch_bounds__(512) base_grid_kernel(
        const float* __restrict__ x_loc, const float* __restrict__ Wr,
        const float* __restrict__ br) {
    int idx = blockIdx.x * 512 + threadIdx.x;
    int b = idx >> 16, n = idx & (NN - 1);
    float x0v = x_loc[(b * 3 + 0) * NN + n];
    float x1v = x_loc[(b * 3 + 1) * NN + n];
    float x2v = x_loc[(b * 3 + 2) * NN + n];
    float g0 = br[0] + Wr[0] * x0v + Wr[1] * x1v + Wr[2] * x2v;
    float g1 = br[1] + Wr[131] * x0v + Wr[132] * x1v + Wr[133] * x2v;
    g_grid0[idx] = g0;
    g_grid1[idx] = g1;
    int x0, x1, y0, y1; float wx, wy;
    point_coords(g0, g1, x0, x1, y0, y1, wx, wy);
    bbox_reduce(b, x0, y0, x1, y1);
}

// ---------------------------------------------------------------------------
// Fallback MLP path (early-exits when Wr[:,3:]==0, as in this dataset).
// When active it grows the bbox; bbox only accumulates so union is safe.
// ---------------------------------------------------------------------------
__global__ void __launch_bounds__(512) mlp_grid_kernel(
        const float* __restrict__ x_loc, const float* __restrict__ x_feat,
        const float* __restrict__ W1, const float* __restrict__ b1,
        const float* __restrict__ W2, const float* __restrict__ b2,
        const float* __restrict__ Wr) {
    if (g_needs_mlp == 0) return;   // uniform branch
    int idx = blockIdx.x * 512 + threadIdx.x;
    int b = idx >> 16, n = idx & (NN - 1);

    float x[67];
    for (int k = 0; k < 3; k++)  x[k] = x_loc[(b * 3 + k) * NN + n];
    for (int k = 0; k < 64; k++) x[3 + k] = x_feat[(b * 64 + k) * NN + n];
    float h1[128];
    for (int j = 0; j < 128; j++) {
        float s = b1[j];
        for (int k = 0; k < 67; k++) s += W1[j * 67 + k] * x[k];
        h1[j] = fmaxf(s, 0.0f);
    }
    float g0 = 0.0f, g1 = 0.0f;
    for (int j = 0; j < 128; j++) {
        float s = b2[j];
        for (int k = 0; k < 128; k++) s += W2[j * 128 + k] * h1[k];
        s = fmaxf(s, 0.0f);
        g0 += Wr[3 + j] * s;
        g1 += Wr[131 + 3 + j] * s;
    }
    g0 += g_grid0[idx];
    g1 += g_grid1[idx];
    g_grid0[idx] = g0;
    g_grid1[idx] = g1;
    int x0, x1, y0, y1; float wx, wy;
    point_coords(g0, g1, x0, x1, y0, y1, wx, wy);
    bbox_reduce(b, x0, y0, x1, y1);
}

// ---------------------------------------------------------------------------
// bbox-gated transpose to flat NHWC fp16. grid (4, 7, 128), block (32,8).
// One block: FOUR y rows, 32 x's, one 64-channel tile (32 in-flight loads
// per thread). Warp stores 64 contiguous fp16 channels (128 B) per texel.
// ---------------------------------------------------------------------------
__global__ void __launch_bounds__(256) transpose_kernel(
        const float* __restrict__ m0, const float* __restrict__ m1,
        const float* __restrict__ m2) {
    int b  = blockIdx.z >> 5;
    int yb = (blockIdx.z & 31) << 2;
    int xt = blockIdx.x << 5;
    int bx0 = g_bbox[b][0], bx1 = g_bbox[b][2];
    int by0 = g_bbox[b][1], by1 = g_bbox[b][3];
    if (yb + 3 < by0 || yb > by1 || xt > bx1 || xt + 31 < bx0) return;

    int ct = blockIdx.y;                   // 7 tiles of 64 channels
    const float* m; int C, c0, coff;
    if (ct == 0)      { m = m0; C = 64;  c0 = 0;             coff = 0; }
    else if (ct < 3)  { m = m1; C = 128; c0 = (ct - 1) * 64; coff = 64 + c0; }
    else              { m = m2; C = 256; c0 = (ct - 3) * 64; coff = 192 + c0; }

    __shared__ float tile[4][64][33];
    int tx = threadIdx.x, ty = threadIdx.y;
    const float* src = m + ((size_t)(b * C + c0 + ty) * (HH * WW)) + yb * WW + xt + tx;
#pragma unroll
    for (int yy = 0; yy < 4; yy++)
#pragma unroll
        for (int i = 0; i < 8; i++)
            tile[yy][ty + i * 8][tx] = src[(size_t)(i * 8) * (HH * WW) + yy * WW];
    __syncthreads();

    // warp w handles x = xt + 4w .. 4w+3; lane = channel pair -> 128 B store
    int w = ty, lane = tx;
#pragma unroll
    for (int yy = 0; yy < 4; yy++)
#pragma unroll
        for (int xi = 0; xi < 4; xi++) {
            int x = (w << 2) + xi;
            __half2 h = __floats2half2_rn(tile[yy][2 * lane][x], tile[yy][2 * lane + 1][x]);
            *(__half2*)&g_t[((size_t)((b * HH + yb + yy) * WW + xt + x)) * C_ALL + coff + 2 * lane] = h;
        }
}

// ---------------------------------------------------------------------------
// Bilinear gather + channel transpose. 64 points/block, 512 threads.
// Warp handles 4 points: lane>>3 = point-sub, lane&7 = channel octet.
// Each lane loads float4 (8 fp16) per texel row -> LDG.128, 512 B/warp.
// Double-buffered stride-65 staging: gather(c+1) overlaps write(c).
// ---------------------------------------------------------------------------
__global__ void __launch_bounds__(512) sample_kernel(float* __restrict__ out) {
    __shared__ float s_w[4][64];
    __shared__ int   s_base[4][64];
    __shared__ float val[2][64 * 65];

    int b   = blockIdx.y;
    int n0  = blockIdx.x << 6;
    int tid = threadIdx.x;
    int lane = tid & 31, w = tid >> 5;

    if (tid < 64) {
        int idx = b * NN + n0 + tid;
        int x0, x1, y0, y1; float wx, wy;
        point_coords(g_grid0[idx], g_grid1[idx], x0, x1, y0, y1, wx, wy);
        s_w[0][tid] = (1.0f - wy) * (1.0f - wx);
        s_w[1][tid] = (1.0f - wy) * wx;
        s_w[2][tid] = wy * (1.0f - wx);
        s_w[3][tid] = wy * wx;
        int r0 = (b * HH + y0) * WW;
        int r1 = (b * HH + y1) * WW;
        s_base[0][tid] = (r0 + x0) * C_ALL;
        s_base[1][tid] = (r0 + x1) * C_ALL;
        s_base[2][tid] = (r1 + x0) * C_ALL;
        s_base[3][tid] = (r1 + x1) * C_ALL;
    }
    __syncthreads();

    int p   = (w << 2) + (lane >> 3);   // this lane's point (0..63)
    int oct = lane & 7;                 // channel octet within 64-ch chunk
    float pw[4];
    int   pb_[4];
#pragma unroll
    for (int t = 0; t < 4; t++) { pw[t] = s_w[t][p]; pb_[t] = s_base[t][p]; }

    // gather chunk into val[buf]
    auto gather = [&](int chunk, int buf) {
        int cc = chunk * 64 + (oct << 3);
        float r[8] = {0.f, 0.f, 0.f, 0.f, 0.f, 0.f, 0.f, 0.f};
#pragma unroll
        for (int t = 0; t < 4; t++) {
            uint4 u = *(const uint4*)&g_t[pb_[t] + cc];
            float wt = pw[t];
#pragma unroll
            for (int k = 0; k < 4; k++) {
                float2 f = __half22float2(((const __half2*)&u)[k]);
                r[2 * k]     += wt * f.x;
                r[2 * k + 1] += wt * f.y;
            }
        }
        float* vp = &val[buf][p * 65 + (oct << 3)];
#pragma unroll
        for (int k = 0; k < 8; k++) vp[k] = r[k];
    };

    gather(0, 0);
    __syncthreads();

#pragma unroll
    for (int chunk = 0; chunk < 7; chunk++) {
        int buf = chunk & 1;
        // prefetch next chunk into the other buffer (overlaps write drain)
        if (chunk + 1 < 7) gather(chunk + 1, buf ^ 1);

        // write: warp w owns channels c0+4w..4w+3, 64 n's each (coalesced)
        int c0 = chunk * 64;
#pragma unroll
        for (int j = 0; j < 4; j++) {
            float* outp = out + ((size_t)(b * C_ALL + c0 + (w << 2) + j)) * NN + n0;
#pragma unroll
            for (int it = 0; it < 2; it++) {
                int n = it * 32 + lane;
                __stcs(&outp[n], val[buf][n * 65 + (w << 2) + j]);
            }
        }
        __syncthreads();
    }
}

// ---------------------------------------------------------------------------
extern "C" void kernel_launch(void* const* d_in, const int* in_sizes, int n_in,
                              void* d_out, int out_size) {
    const float* x_loc  = (const float*)d_in[0];
    const float* x_feat = (const float*)d_in[1];
    const float* m0     = (const float*)d_in[2];
    const float* m1     = (const float*)d_in[3];
    const float* m2     = (const float*)d_in[4];
    const float* W1     = (const float*)d_in[5];
    const float* b1     = (const float*)d_in[6];
    const float* W2     = (const float*)d_in[7];
    const float* b2     = (const float*)d_in[8];
    const float* Wr     = (const float*)d_in[9];
    const float* br     = (const float*)d_in[10];
    float* out = (float*)d_out;

    check_wr_kernel<<<1, 256>>>(Wr);
    base_grid_kernel<<<512, 512>>>(x_loc, Wr, br);
    mlp_grid_kernel<<<512, 512>>>(x_loc, x_feat, W1, b1, W2, b2, Wr);
    transpose_kernel<<<dim3(4, 7, 128), dim3(32, 8)>>>(m0, m1, m2);
    sample_kernel<<<dim3(NN / 64, BB), 512>>>(out);
}

// round 10
// speedup vs baseline: 2.7682x; 1.0298x over previous
#include <cuda_runtime.h>
#include <cuda_fp16.h>
#include <climits>

#define BB 4
#define NN 65536
#define HH 128
#define WW 128
#define C_ALL 448   // 64 + 128 + 256

// fused NHWC fp16 scratch [b][y][x][448], 56 MB
__device__ __half g_t[(size_t)BB * HH * WW * C_ALL];
__device__ float  g_grid0[BB * NN];
__device__ float  g_grid1[BB * NN];
__device__ int    g_bbox[BB][4];   // minx0, miny0, maxx1, maxy1
__device__ int    g_needs_mlp;

// ---------------------------------------------------------------------------
__device__ __forceinline__ void point_coords(float gx, float gy,
                                             int& x0, int& x1, int& y0, int& y1,
                                             float& wx, float& wy) {
    float ix = ((gx + 1.0f) * 128.0f - 1.0f) * 0.5f;
    float iy = ((gy + 1.0f) * 128.0f - 1.0f) * 0.5f;
    ix = fminf(fmaxf(ix, 0.0f), 127.0f);
    iy = fminf(fmaxf(iy, 0.0f), 127.0f);
    float fx0 = floorf(ix), fy0 = floorf(iy);
    wx = ix - fx0; wy = iy - fy0;
    x0 = (int)fx0; y0 = (int)fy0;
    x1 = min(x0 + 1, 127); y1 = min(y0 + 1, 127);
}

// Block-wide bbox reduce; 512-thread block, all threads same batch b.
__device__ __forceinline__ void bbox_reduce(int b, int x0, int y0,
                                            int x1, int y1) {
    __shared__ int sm[4][16];
    int mnx = __reduce_min_sync(0xffffffffu, x0);
    int mny = __reduce_min_sync(0xffffffffu, y0);
    int mxx = __reduce_max_sync(0xffffffffu, x1);
    int mxy = __reduce_max_sync(0xffffffffu, y1);
    int w = threadIdx.x >> 5;
    if ((threadIdx.x & 31) == 0) {
        sm[0][w] = mnx; sm[1][w] = mny; sm[2][w] = mxx; sm[3][w] = mxy;
    }
    __syncthreads();
    if (threadIdx.x == 0) {
        int a0 = sm[0][0], a1 = sm[1][0], a2 = sm[2][0], a3 = sm[3][0];
#pragma unroll
        for (int i = 1; i < 16; i++) {
            a0 = min(a0, sm[0][i]); a1 = min(a1, sm[1][i]);
            a2 = max(a2, sm[2][i]); a3 = max(a3, sm[3][i]);
        }
        atomicMin(&g_bbox[b][0], a0); atomicMin(&g_bbox[b][1], a1);
        atomicMax(&g_bbox[b][2], a2); atomicMax(&g_bbox[b][3], a3);
    }
}

// ---------------------------------------------------------------------------
__global__ void check_wr_kernel(const float* __restrict__ Wr) {
    if (threadIdx.x < BB) {
        g_bbox[threadIdx.x][0] = INT_MAX; g_bbox[threadIdx.x][1] = INT_MAX;
        g_bbox[threadIdx.x][2] = INT_MIN; g_bbox[threadIdx.x][3] = INT_MIN;
    }
    int nz = 0;
    for (int idx = threadIdx.x; idx < 2 * 131; idx += blockDim.x) {
        int k = idx % 131;
        if (k >= 3 && Wr[idx] != 0.0f) nz = 1;
    }
    int any = __syncthreads_or(nz);
    if (threadIdx.x == 0) g_needs_mlp = any;
}

// ---------------------------------------------------------------------------
// Base grid + fused bbox. 512 blocks x 512 threads; block spans one batch.
// ---------------------------------------------------------------------------
__global__ void __launch_bounds__(512) base_grid_kernel(
        const float* __restrict__ x_loc, const float* __restrict__ Wr,
        const float* __restrict__ br) {
    int idx = blockIdx.x * 512 + threadIdx.x;
    int b = idx >> 16, n = idx & (NN - 1);
    float x0v = x_loc[(b * 3 + 0) * NN + n];
    float x1v = x_loc[(b * 3 + 1) * NN + n];
    float x2v = x_loc[(b * 3 + 2) * NN + n];
    float g0 = br[0] + Wr[0] * x0v + Wr[1] * x1v + Wr[2] * x2v;
    float g1 = br[1] + Wr[131] * x0v + Wr[132] * x1v + Wr[133] * x2v;
    g_grid0[idx] = g0;
    g_grid1[idx] = g1;
    int x0, x1, y0, y1; float wx, wy;
    point_coords(g0, g1, x0, x1, y0, y1, wx, wy);
    bbox_reduce(b, x0, y0, x1, y1);
}

// ---------------------------------------------------------------------------
// Fallback MLP path (early-exits when Wr[:,3:]==0, as in this dataset).
// When active it grows the bbox; bbox only accumulates so union is safe.
// ---------------------------------------------------------------------------
__global__ void __launch_bounds__(512) mlp_grid_kernel(
        const float* __restrict__ x_loc, const float* __restrict__ x_feat,
        const float* __restrict__ W1, const float* __restrict__ b1,
        const float* __restrict__ W2, const float* __restrict__ b2,
        const float* __restrict__ Wr) {
    if (g_needs_mlp == 0) return;   // uniform branch
    int idx = blockIdx.x * 512 + threadIdx.x;
    int b = idx >> 16, n = idx & (NN - 1);

    float x[67];
    for (int k = 0; k < 3; k++)  x[k] = x_loc[(b * 3 + k) * NN + n];
    for (int k = 0; k < 64; k++) x[3 + k] = x_feat[(b * 64 + k) * NN + n];
    float h1[128];
    for (int j = 0; j < 128; j++) {
        float s = b1[j];
        for (int k = 0; k < 67; k++) s += W1[j * 67 + k] * x[k];
        h1[j] = fmaxf(s, 0.0f);
    }
    float g0 = 0.0f, g1 = 0.0f;
    for (int j = 0; j < 128; j++) {
        float s = b2[j];
        for (int k = 0; k < 128; k++) s += W2[j * 128 + k] * h1[k];
        s = fmaxf(s, 0.0f);
        g0 += Wr[3 + j] * s;
        g1 += Wr[131 + 3 + j] * s;
    }
    g0 += g_grid0[idx];
    g1 += g_grid1[idx];
    g_grid0[idx] = g0;
    g_grid1[idx] = g1;
    int x0, x1, y0, y1; float wx, wy;
    point_coords(g0, g1, x0, x1, y0, y1, wx, wy);
    bbox_reduce(b, x0, y0, x1, y1);
}

// ---------------------------------------------------------------------------
// bbox-gated transpose to flat NHWC fp16 (measured-best R8 config).
// grid (4, 7, 256), block (32,8). One block: TWO y rows, 32 x's, one
// 64-channel tile. Warp stores 64 contiguous fp16 channels (128 B)/texel.
// ---------------------------------------------------------------------------
__global__ void __launch_bounds__(256) transpose_kernel(
        const float* __restrict__ m0, const float* __restrict__ m1,
        const float* __restrict__ m2) {
    int b  = blockIdx.z >> 6;
    int yb = (blockIdx.z & 63) << 1;
    int xt = blockIdx.x << 5;
    int bx0 = g_bbox[b][0], bx1 = g_bbox[b][2];
    int by0 = g_bbox[b][1], by1 = g_bbox[b][3];
    if (yb + 1 < by0 || yb > by1 || xt > bx1 || xt + 31 < bx0) return;

    int ct = blockIdx.y;                   // 7 tiles of 64 channels
    const float* m; int C, c0, coff;
    if (ct == 0)      { m = m0; C = 64;  c0 = 0;             coff = 0; }
    else if (ct < 3)  { m = m1; C = 128; c0 = (ct - 1) * 64; coff = 64 + c0; }
    else              { m = m2; C = 256; c0 = (ct - 3) * 64; coff = 192 + c0; }

    __shared__ float tile[2][64][33];
    int tx = threadIdx.x, ty = threadIdx.y;
    const float* src = m + ((size_t)(b * C + c0 + ty) * (HH * WW)) + yb * WW + xt + tx;
#pragma unroll
    for (int yy = 0; yy < 2; yy++)
#pragma unroll
        for (int i = 0; i < 8; i++)
            tile[yy][ty + i * 8][tx] = src[(size_t)(i * 8) * (HH * WW) + yy * WW];
    __syncthreads();

    // warp w handles x = xt + 4w .. 4w+3; lane = channel pair -> 128 B store
    int w = ty, lane = tx;
#pragma unroll
    for (int yy = 0; yy < 2; yy++)
#pragma unroll
        for (int xi = 0; xi < 4; xi++) {
            int x = (w << 2) + xi;
            __half2 h = __floats2half2_rn(tile[yy][2 * lane][x], tile[yy][2 * lane + 1][x]);
            *(__half2*)&g_t[((size_t)((b * HH + yb + yy) * WW + xt + x)) * C_ALL + coff + 2 * lane] = h;
        }
}

// ---------------------------------------------------------------------------
// Bilinear gather + channel transpose. 64 points/block, 512 threads.
// Warp handles 4 points: lane>>3 = point-sub, lane&7 = channel octet.
// Each lane loads float4 (8 fp16) per texel row -> LDG.128, 512 B/warp.
// Double-buffered stride-65 staging: gather(c+1) overlaps write(c).
// ---------------------------------------------------------------------------
__global__ void __launch_bounds__(512) sample_kernel(float* __restrict__ out) {
    __shared__ float s_w[4][64];
    __shared__ int   s_base[4][64];
    __shared__ float val[2][64 * 65];

    int b   = blockIdx.y;
    int n0  = blockIdx.x << 6;
    int tid = threadIdx.x;
    int lane = tid & 31, w = tid >> 5;

    if (tid < 64) {
        int idx = b * NN + n0 + tid;
        int x0, x1, y0, y1; float wx, wy;
        point_coords(g_grid0[idx], g_grid1[idx], x0, x1, y0, y1, wx, wy);
        s_w[0][tid] = (1.0f - wy) * (1.0f - wx);
        s_w[1][tid] = (1.0f - wy) * wx;
        s_w[2][tid] = wy * (1.0f - wx);
        s_w[3][tid] = wy * wx;
        int r0 = (b * HH + y0) * WW;
        int r1 = (b * HH + y1) * WW;
        s_base[0][tid] = (r0 + x0) * C_ALL;
        s_base[1][tid] = (r0 + x1) * C_ALL;
        s_base[2][tid] = (r1 + x0) * C_ALL;
        s_base[3][tid] = (r1 + x1) * C_ALL;
    }
    __syncthreads();

    int p   = (w << 2) + (lane >> 3);   // this lane's point (0..63)
    int oct = lane & 7;                 // channel octet within 64-ch chunk
    float pw[4];
    int   pb_[4];
#pragma unroll
    for (int t = 0; t < 4; t++) { pw[t] = s_w[t][p]; pb_[t] = s_base[t][p]; }

    // gather chunk into val[buf]
    auto gather = [&](int chunk, int buf) {
        int cc = chunk * 64 + (oct << 3);
        float r[8] = {0.f, 0.f, 0.f, 0.f, 0.f, 0.f, 0.f, 0.f};
#pragma unroll
        for (int t = 0; t < 4; t++) {
            uint4 u = *(const uint4*)&g_t[pb_[t] + cc];
            float wt = pw[t];
#pragma unroll
            for (int k = 0; k < 4; k++) {
                float2 f = __half22float2(((const __half2*)&u)[k]);
                r[2 * k]     += wt * f.x;
                r[2 * k + 1] += wt * f.y;
            }
        }
        float* vp = &val[buf][p * 65 + (oct << 3)];
#pragma unroll
        for (int k = 0; k < 8; k++) vp[k] = r[k];
    };

    gather(0, 0);
    __syncthreads();

#pragma unroll
    for (int chunk = 0; chunk < 7; chunk++) {
        int buf = chunk & 1;
        // prefetch next chunk into the other buffer (overlaps write drain)
        if (chunk + 1 < 7) gather(chunk + 1, buf ^ 1);

        // write: warp w owns channels c0+4w..4w+3, 64 n's each (coalesced)
        int c0 = chunk * 64;
#pragma unroll
        for (int j = 0; j < 4; j++) {
            float* outp = out + ((size_t)(b * C_ALL + c0 + (w << 2) + j)) * NN + n0;
#pragma unroll
            for (int it = 0; it < 2; it++) {
                int n = it * 32 + lane;
                __stcs(&outp[n], val[buf][n * 65 + (w << 2) + j]);
            }
        }
        __syncthreads();
    }
}

// ---------------------------------------------------------------------------
extern "C" void kernel_launch(void* const* d_in, const int* in_sizes, int n_in,
                              void* d_out, int out_size) {
    const float* x_loc  = (const float*)d_in[0];
    const float* x_feat = (const float*)d_in[1];
    const float* m0     = (const float*)d_in[2];
    const float* m1     = (const float*)d_in[3];
    const float* m2     = (const float*)d_in[4];
    const float* W1     = (const float*)d_in[5];
    const float* b1     = (const float*)d_in[6];
    const float* W2     = (const float*)d_in[7];
    const float* b2     = (const float*)d_in[8];
    const float* Wr     = (const float*)d_in[9];
    const float* br     = (const float*)d_in[10];
    float* out = (float*)d_out;

    check_wr_kernel<<<1, 256>>>(Wr);
    base_grid_kernel<<<512, 512>>>(x_loc, Wr, br);
    mlp_grid_kernel<<<512, 512>>>(x_loc, x_feat, W1, b1, W2, b2, Wr);
    transpose_kernel<<<dim3(4, 7, 256), dim3(32, 8)>>>(m0, m1, m2);
    sample_kernel<<<dim3(NN / 64, BB), 512>>>(out);
}

// round 12
// speedup vs baseline: 2.8610x; 1.0335x over previous
#include <cuda_runtime.h>
#include <cuda_fp16.h>
#include <climits>

#define BB 4
#define NN 65536
#define HH 128
#define WW 128
#define C_ALL 448   // 64 + 128 + 256

// fused NHWC fp16 scratch [b][y][x][448], 56 MB
__device__ __half g_t[(size_t)BB * HH * WW * C_ALL];
__device__ float  g_grid0[BB * NN];
__device__ float  g_grid1[BB * NN];
// bbox sentinels: statically initialized; re-armed by sample_kernel each run
// (sample never reads bbox, so the reset is safely ordered for the NEXT run).
__device__ int g_bbox[BB][4] = {
    {INT_MAX, INT_MAX, INT_MIN, INT_MIN}, {INT_MAX, INT_MAX, INT_MIN, INT_MIN},
    {INT_MAX, INT_MAX, INT_MIN, INT_MIN}, {INT_MAX, INT_MAX, INT_MIN, INT_MIN}};

// ---------------------------------------------------------------------------
__device__ __forceinline__ void point_coords(float gx, float gy,
                                             int& x0, int& x1, int& y0, int& y1,
                                             float& wx, float& wy) {
    float ix = ((gx + 1.0f) * 128.0f - 1.0f) * 0.5f;
    float iy = ((gy + 1.0f) * 128.0f - 1.0f) * 0.5f;
    ix = fminf(fmaxf(ix, 0.0f), 127.0f);
    iy = fminf(fmaxf(iy, 0.0f), 127.0f);
    float fx0 = floorf(ix), fy0 = floorf(iy);
    wx = ix - fx0; wy = iy - fy0;
    x0 = (int)fx0; y0 = (int)fy0;
    x1 = min(x0 + 1, 127); y1 = min(y0 + 1, 127);
}

// Block-wide bbox reduce; 512-thread block, all threads same batch b.
__device__ __forceinline__ void bbox_reduce(int b, int x0, int y0,
                                            int x1, int y1) {
    __shared__ int sm[4][16];
    int mnx = __reduce_min_sync(0xffffffffu, x0);
    int mny = __reduce_min_sync(0xffffffffu, y0);
    int mxx = __reduce_max_sync(0xffffffffu, x1);
    int mxy = __reduce_max_sync(0xffffffffu, y1);
    int w = threadIdx.x >> 5;
    if ((threadIdx.x & 31) == 0) {
        sm[0][w] = mnx; sm[1][w] = mny; sm[2][w] = mxx; sm[3][w] = mxy;
    }
    __syncthreads();
    if (threadIdx.x == 0) {
        int a0 = sm[0][0], a1 = sm[1][0], a2 = sm[2][0], a3 = sm[3][0];
#pragma unroll
        for (int i = 1; i < 16; i++) {
            a0 = min(a0, sm[0][i]); a1 = min(a1, sm[1][i]);
            a2 = max(a2, sm[2][i]); a3 = max(a3, sm[3][i]);
        }
        atomicMin(&g_bbox[b][0], a0); atomicMin(&g_bbox[b][1], a1);
        atomicMax(&g_bbox[b][2], a2); atomicMax(&g_bbox[b][3], a3);
    }
}

// ---------------------------------------------------------------------------
// Base grid + fused bbox. 512 blocks x 512 threads; block spans one batch.
// ---------------------------------------------------------------------------
__global__ void __launch_bounds__(512) base_grid_kernel(
        const float* __restrict__ x_loc, const float* __restrict__ Wr,
        const float* __restrict__ br) {
    int idx = blockIdx.x * 512 + threadIdx.x;
    int b = idx >> 16, n = idx & (NN - 1);
    float x0v = x_loc[(b * 3 + 0) * NN + n];
    float x1v = x_loc[(b * 3 + 1) * NN + n];
    float x2v = x_loc[(b * 3 + 2) * NN + n];
    float g0 = br[0] + Wr[0] * x0v + Wr[1] * x1v + Wr[2] * x2v;
    float g1 = br[1] + Wr[131] * x0v + Wr[132] * x1v + Wr[133] * x2v;
    g_grid0[idx] = g0;
    g_grid1[idx] = g1;
    int x0, x1, y0, y1; float wx, wy;
    point_coords(g0, g1, x0, x1, y0, y1, wx, wy);
    bbox_reduce(b, x0, y0, x1, y1);
}

// ---------------------------------------------------------------------------
// Fallback MLP path. Each block first checks (from L2) whether Wr touches
// the MLP features at all; early-exits when not (the benched case). When
// active it grows the bbox; bbox only accumulates so the union is safe.
// ---------------------------------------------------------------------------
__global__ void __launch_bounds__(512) mlp_grid_kernel(
        const float* __restrict__ x_loc, const float* __restrict__ x_feat,
        const float* __restrict__ W1, const float* __restrict__ b1,
        const float* __restrict__ W2, const float* __restrict__ b2,
        const float* __restrict__ Wr) {
    {
        int t = threadIdx.x, nz = 0;
        if (t < 262) {
            int row = t / 131, k = t % 131;
            if (k >= 3 && Wr[row * 131 + k] != 0.0f) nz = 1;
        }
        if (__syncthreads_or(nz) == 0) return;
    }
    int idx = blockIdx.x * 512 + threadIdx.x;
    int b = idx >> 16, n = idx & (NN - 1);

    float x[67];
    for (int k = 0; k < 3; k++)  x[k] = x_loc[(b * 3 + k) * NN + n];
    for (int k = 0; k < 64; k++) x[3 + k] = x_feat[(b * 64 + k) * NN + n];
    float h1[128];
    for (int j = 0; j < 128; j++) {
        float s = b1[j];
        for (int k = 0; k < 67; k++) s += W1[j * 67 + k] * x[k];
        h1[j] = fmaxf(s, 0.0f);
    }
    float g0 = 0.0f, g1 = 0.0f;
    for (int j = 0; j < 128; j++) {
        float s = b2[j];
        for (int k = 0; k < 128; k++) s += W2[j * 128 + k] * h1[k];
        s = fmaxf(s, 0.0f);
        g0 += Wr[3 + j] * s;
        g1 += Wr[131 + 3 + j] * s;
    }
    g0 += g_grid0[idx];
    g1 += g_grid1[idx];
    g_grid0[idx] = g0;
    g_grid1[idx] = g1;
    int x0, x1, y0, y1; float wx, wy;
    point_coords(g0, g1, x0, x1, y0, y1, wx, wy);
    bbox_reduce(b, x0, y0, x1, y1);
}

// ---------------------------------------------------------------------------
// bbox-gated transpose to flat NHWC fp16. grid (4, 7, 256), block = 256
// FLAT threads. TWO y rows, 32 x's, one 64-channel tile per block. Loads
// are 4x LDG.128 per thread; warp stores 64 contiguous fp16 (128 B)/texel.
// ---------------------------------------------------------------------------
__global__ void __launch_bounds__(256) transpose_kernel(
        const float* __restrict__ m0, const float* __restrict__ m1,
        const float* __restrict__ m2) {
    int b  = blockIdx.z >> 6;
    int yb = (blockIdx.z & 63) << 1;
    int xt = blockIdx.x << 5;
    int bx0 = g_bbox[b][0], bx1 = g_bbox[b][2];
    int by0 = g_bbox[b][1], by1 = g_bbox[b][3];
    if (yb + 1 < by0 || yb > by1 || xt > bx1 || xt + 31 < bx0) return;

    int ct = blockIdx.y;                   // 7 tiles of 64 channels
    const float* m; int C, c0, coff;
    if (ct == 0)      { m = m0; C = 64;  c0 = 0;             coff = 0; }
    else if (ct < 3)  { m = m1; C = 128; c0 = (ct - 1) * 64; coff = 64 + c0; }
    else              { m = m2; C = 256; c0 = (ct - 3) * 64; coff = 192 + c0; }

    __shared__ float tile[2][64][33];
    int tid = threadIdx.x;                 // FLAT 0..255
    // 1024 16B granules: g -> (q = x-quad, c, yy); consecutive tid = coalesced
#pragma unroll
    for (int i = 0; i < 4; i++) {
        int g = tid + i * 256;
        int q = g & 7, c = (g >> 3) & 63, yy = g >> 9;
        float4 v = *(const float4*)(m + ((size_t)(b * C + c0 + c) * HH + yb + yy) * WW + xt + q * 4);
        float* dst = &tile[yy][c][q * 4];
        dst[0] = v.x; dst[1] = v.y; dst[2] = v.z; dst[3] = v.w;
    }
    __syncthreads();

    // warp w handles x = xt + 4w .. 4w+3; lane = channel pair -> 128 B store
    int w = tid >> 5, lane = tid & 31;
#pragma unroll
    for (int yy = 0; yy < 2; yy++)
#pragma unroll
        for (int xi = 0; xi < 4; xi++) {
            int x = (w << 2) + xi;
            __half2 h = __floats2half2_rn(tile[yy][2 * lane][x], tile[yy][2 * lane + 1][x]);
            *(__half2*)&g_t[((size_t)((b * HH + yb + yy) * WW + xt + x)) * C_ALL + coff + 2 * lane] = h;
        }
}

// ---------------------------------------------------------------------------
// Bilinear gather + channel transpose. 64 points/block, 512 threads.
// Warp handles 4 points: lane>>3 = point-sub, lane&7 = channel octet.
// Each lane loads float4 (8 fp16) per texel row -> LDG.128, 512 B/warp.
// Double-buffered stride-65 staging: gather(c+1) overlaps write(c).
// Block (0,0) re-arms the bbox sentinels for the next replay (bbox is not
// read in this kernel, and this launch follows transpose in stream order).
// ---------------------------------------------------------------------------
__global__ void __launch_bounds__(512) sample_kernel(float* __restrict__ out) {
    __shared__ float s_w[4][64];
    __shared__ int   s_base[4][64];
    __shared__ float val[2][64 * 65];

    int b   = blockIdx.y;
    int n0  = blockIdx.x << 6;
    int tid = threadIdx.x;
    int lane = tid & 31, w = tid >> 5;

    if (blockIdx.x == 0 && blockIdx.y == 0 && tid < 16)
        ((int*)g_bbox)[tid] = ((tid & 3) < 2) ? INT_MAX : INT_MIN;

    if (tid < 64) {
        int idx = b * NN + n0 + tid;
        int x0, x1, y0, y1; float wx, wy;
        point_coords(g_grid0[idx], g_grid1[idx], x0, x1, y0, y1, wx, wy);
        s_w[0][tid] = (1.0f - wy) * (1.0f - wx);
        s_w[1][tid] = (1.0f - wy) * wx;
        s_w[2][tid] = wy * (1.0f - wx);
        s_w[3][tid] = wy * wx;
        int r0 = (b * HH + y0) * WW;
        int r1 = (b * HH + y1) * WW;
        s_base[0][tid] = (r0 + x0) * C_ALL;
        s_base[1][tid] = (r0 + x1) * C_ALL;
        s_base[2][tid] = (r1 + x0) * C_ALL;
        s_base[3][tid] = (r1 + x1) * C_ALL;
    }
    __syncthreads();

    int p   = (w << 2) + (lane >> 3);   // this lane's point (0..63)
    int oct = lane & 7;                 // channel octet within 64-ch chunk
    float pw[4];
    int   pb_[4];
#pragma unroll
    for (int t = 0; t < 4; t++) { pw[t] = s_w[t][p]; pb_[t] = s_base[t][p]; }

    auto gather = [&](int chunk, int buf) {
        int cc = chunk * 64 + (oct << 3);
        float r[8] = {0.f, 0.f, 0.f, 0.f, 0.f, 0.f, 0.f, 0.f};
#pragma unroll
        for (int t = 0; t < 4; t++) {
            uint4 u = *(const uint4*)&g_t[pb_[t] + cc];
            float wt = pw[t];
#pragma unroll
            for (int k = 0; k < 4; k++) {
                float2 f = __half22float2(((const __half2*)&u)[k]);
                r[2 * k]     += wt * f.x;
                r[2 * k + 1] += wt * f.y;
            }
        }
        float* vp = &val[buf][p * 65 + (oct << 3)];
#pragma unroll
        for (int k = 0; k < 8; k++) vp[k] = r[k];
    };

    gather(0, 0);
    __syncthreads();

#pragma unroll
    for (int chunk = 0; chunk < 7; chunk++) {
        int buf = chunk & 1;
        if (chunk + 1 < 7) gather(chunk + 1, buf ^ 1);

        int c0 = chunk * 64;
#pragma unroll
        for (int j = 0; j < 4; j++) {
            float* outp = out + ((size_t)(b * C_ALL + c0 + (w << 2) + j)) * NN + n0;
#pragma unroll
            for (int it = 0; it < 2; it++) {
                int n = it * 32 + lane;
                __stcs(&outp[n], val[buf][n * 65 + (w << 2) + j]);
            }
        }
        __syncthreads();
    }
}

// ---------------------------------------------------------------------------
extern "C" void kernel_launch(void* const* d_in, const int* in_sizes, int n_in,
                              void* d_out, int out_size) {
    const float* x_loc  = (const float*)d_in[0];
    const float* x_feat = (const float*)d_in[1];
    const float* m0     = (const float*)d_in[2];
    const float* m1     = (const float*)d_in[3];
    const float* m2     = (const float*)d_in[4];
    const float* W1     = (const float*)d_in[5];
    const float* b1     = (const float*)d_in[6];
    const float* W2     = (const float*)d_in[7];
    const float* b2     = (const float*)d_in[8];
    const float* Wr     = (const float*)d_in[9];
    const float* br     = (const float*)d_in[10];
    float* out = (float*)d_out;

    base_grid_kernel<<<512, 512>>>(x_loc, Wr, br);
    mlp_grid_kernel<<<512, 512>>>(x_loc, x_feat, W1, b1, W2, b2, Wr);
    transpose_kernel<<<dim3(4, 7, 256), 256>>>(m0, m1, m2);
    sample_kernel<<<dim3(NN / 64, BB), 512>>>(out);
}